// round 4
// baseline (speedup 1.0000x reference)
#include <cuda_runtime.h>
#include <cuda_bf16.h>
#include <math.h>
#include <string.h>

// ============================================================================
// Problem constants (fixed by the dataset)
// ============================================================================
#define NN    20000          // nodes
#define NGR   5000           // graphs
#define MIDW  368            // dim of IR_MID
#define GSTR  816            // 16 * 51 (per-node G row)

// ============================================================================
// Device scratch (static — no allocation allowed)
// ============================================================================
__device__ float4 g_G4[(size_t)NN * GSTR / 4];      // 65.3 MB geometric accumulators
__device__ float  g_node_sh[(size_t)NN * 9];        // raw SH sums per node
__device__ float  g_node_mid[(size_t)NN * MIDW];    // mid features per node

// ============================================================================
// Parameter structs (filled on host at capture time, passed by value)
// ============================================================================
struct W3JP {
    float c000;
    float c011[9],  c022[25], c101[9],  c110[9];
    float c111[27], c112[45], c121[45], c122[75];
    float c202[25], c211[45], c212[75];
    float c220[25], c221[75], c222[125];
};
struct TP2P { float c110[9]; float c220[25]; float c000; float s20, s21; };
struct S1P  { float s1[5]; };

// ============================================================================
// Device helpers
// ============================================================================
__device__ __forceinline__ void compute_sh(float x, float y, float z, float sh[9]) {
    const float s3  = 1.7320508075688772f;
    const float s15 = 3.8729833462074170f;
    const float s5  = 2.2360679774997896f;
    float r2 = x * x + y * y + z * z;
    sh[0] = 1.0f;
    sh[1] = s3 * y; sh[2] = s3 * z; sh[3] = s3 * x;
    sh[4] = s15 * x * y;
    sh[5] = s15 * y * z;
    sh[6] = 0.5f * s5 * (3.0f * z * z - r2);
    sh[7] = s15 * x * z;
    sh[8] = 0.5f * s15 * (x * x - y * y);
}

// ============================================================================
// K0: zero scratch + output
// ============================================================================
__global__ void k_zero(float* __restrict__ out, int outN) {
    size_t idx    = (size_t)blockIdx.x * blockDim.x + threadIdx.x;
    size_t stride = (size_t)gridDim.x * blockDim.x;
    const float4 z4 = make_float4(0.f, 0.f, 0.f, 0.f);
    const size_t ng4 = (size_t)NN * GSTR / 4;
    for (size_t j = idx; j < ng4; j += stride) g_G4[j] = z4;
    for (size_t j = idx; j < (size_t)NN * 9; j += stride) g_node_sh[j] = 0.f;
    for (size_t j = idx; j < (size_t)outN; j += stride) out[j] = 0.f;
}

// ============================================================================
// K1: per-edge SH -> atomic accumulate into node_sh[dst] (raw, unscaled)
// ============================================================================
__global__ void k_sh(const float* __restrict__ pos,
                     const int* __restrict__ esrc, const int* __restrict__ edst, int E) {
    int e = blockIdx.x * blockDim.x + threadIdx.x;
    if (e >= E) return;
    int s = __ldg(esrc + e), d = __ldg(edst + e);
    float x = __ldg(pos + 3 * s + 0) - __ldg(pos + 3 * d + 0);
    float y = __ldg(pos + 3 * s + 1) - __ldg(pos + 3 * d + 1);
    float z = __ldg(pos + 3 * s + 2) - __ldg(pos + 3 * d + 2);
    float sh[9];
    compute_sh(x, y, z, sh);
    float* np = &g_node_sh[(size_t)d * 9];
#pragma unroll
    for (int i = 0; i < 9; i++) atomicAdd(np + i, sh[i]);
}

// ============================================================================
// K2: per-edge TP1 geometry -> 51 atomics into G[dst][t]
//     g_p[k] = sum_ij xa_a[i] * sh_b[j] * C^{l1 l2 l3}[i,j,k]
// ============================================================================
__global__ void k_tp1(const float* __restrict__ pos, const int* __restrict__ zarr,
                      const int* __restrict__ esrc, const int* __restrict__ edst,
                      int E, W3JP P) {
    int e = blockIdx.x * blockDim.x + threadIdx.x;
    if (e >= E) return;
    int s = __ldg(esrc + e), d = __ldg(edst + e);
    float x = __ldg(pos + 3 * s + 0) - __ldg(pos + 3 * d + 0);
    float y = __ldg(pos + 3 * s + 1) - __ldg(pos + 3 * d + 1);
    float z = __ldg(pos + 3 * s + 2) - __ldg(pos + 3 * d + 2);
    float sh[9];
    compute_sh(x, y, z, sh);
    float xa[9];
    const float* ns = &g_node_sh[(size_t)s * 9];
#pragma unroll
    for (int i = 0; i < 9; i++) xa[i] = ns[i];
    int t = 4 * __ldg(zarr + s) + __ldg(zarr + d);

    float g[51];
#pragma unroll
    for (int m = 0; m < 51; m++) g[m] = 0.f;

    float xa0 = xa[0];
    // p0: (0,0,0) -> goff 0
    g[0] = xa0 * P.c000;                       // sh[0] == 1
    // p1: (0,1,1) -> goff 1
#pragma unroll
    for (int j = 0; j < 3; j++) {
        float f = xa0 * sh[1 + j];
#pragma unroll
        for (int k = 0; k < 3; k++) g[1 + k] += f * P.c011[j * 3 + k];
    }
    // p2: (0,2,2) -> goff 4
#pragma unroll
    for (int j = 0; j < 5; j++) {
        float f = xa0 * sh[4 + j];
#pragma unroll
        for (int k = 0; k < 5; k++) g[4 + k] += f * P.c022[j * 5 + k];
    }
    // p3: (1,0,1) -> goff 9   (sh[0]==1)
#pragma unroll
    for (int i = 0; i < 3; i++) {
        float f = xa[1 + i];
#pragma unroll
        for (int k = 0; k < 3; k++) g[9 + k] += f * P.c101[i * 3 + k];
    }
    // p4 (1,1,0)->goff 12, p5 (1,1,1)->13, p6 (1,1,2)->16
#pragma unroll
    for (int i = 0; i < 3; i++) {
#pragma unroll
        for (int j = 0; j < 3; j++) {
            float f = xa[1 + i] * sh[1 + j];
            g[12] += f * P.c110[i * 3 + j];
#pragma unroll
            for (int k = 0; k < 3; k++) g[13 + k] += f * P.c111[(i * 3 + j) * 3 + k];
#pragma unroll
            for (int k = 0; k < 5; k++) g[16 + k] += f * P.c112[(i * 3 + j) * 5 + k];
        }
    }
    // p7 (1,2,1)->21, p8 (1,2,2)->24
#pragma unroll
    for (int i = 0; i < 3; i++) {
#pragma unroll
        for (int j = 0; j < 5; j++) {
            float f = xa[1 + i] * sh[4 + j];
#pragma unroll
            for (int k = 0; k < 3; k++) g[21 + k] += f * P.c121[(i * 5 + j) * 3 + k];
#pragma unroll
            for (int k = 0; k < 5; k++) g[24 + k] += f * P.c122[(i * 5 + j) * 5 + k];
        }
    }
    // p9 (2,0,2)->29
#pragma unroll
    for (int i = 0; i < 5; i++) {
        float f = xa[4 + i];
#pragma unroll
        for (int k = 0; k < 5; k++) g[29 + k] += f * P.c202[i * 5 + k];
    }
    // p10 (2,1,1)->34, p11 (2,1,2)->37
#pragma unroll
    for (int i = 0; i < 5; i++) {
#pragma unroll
        for (int j = 0; j < 3; j++) {
            float f = xa[4 + i] * sh[1 + j];
#pragma unroll
            for (int k = 0; k < 3; k++) g[34 + k] += f * P.c211[(i * 3 + j) * 3 + k];
#pragma unroll
            for (int k = 0; k < 5; k++) g[37 + k] += f * P.c212[(i * 3 + j) * 5 + k];
        }
    }
    // p12 (2,2,0)->42, p13 (2,2,1)->43, p14 (2,2,2)->46
#pragma unroll
    for (int i = 0; i < 5; i++) {
#pragma unroll
        for (int j = 0; j < 5; j++) {
            float f = xa[4 + i] * sh[4 + j];
            g[42] += f * P.c220[i * 5 + j];
#pragma unroll
            for (int k = 0; k < 3; k++) g[43 + k] += f * P.c221[(i * 5 + j) * 3 + k];
#pragma unroll
            for (int k = 0; k < 5; k++) g[46 + k] += f * P.c222[(i * 5 + j) * 5 + k];
        }
    }

    float* Gf = reinterpret_cast<float*>(g_G4);
    float* Gp = &Gf[((size_t)d * 16 + t) * 51];
#pragma unroll
    for (int m = 0; m < 51; m++) atomicAdd(Gp + m, g[m]);
}

// ============================================================================
// K3: per-node dense transform  node_mid[n] = s1_c * sum_{p->c, t} W1[p][t][w] * G[n][t][goff_p + k]
//     one block (160 threads) per node; G row cached in shared.
// ============================================================================
__global__ void k_mid(const float* __restrict__ w1, S1P S) {
    __shared__ float sG[GSTR];
    int n = blockIdx.x;
    const float* Gf = reinterpret_cast<const float*>(g_G4);
    for (int i = threadIdx.x; i < GSTR; i += blockDim.x) sG[i] = Gf[(size_t)n * GSTR + i];
    __syncthreads();
    int tid = threadIdx.x;
    if (tid >= 144) return;
    float* outp = &g_node_mid[(size_t)n * MIDW];

    if (tid < 64) {                       // c0: m3=64; p0(0,g0) p4(2048,12) p12(5248,42)
        int w = tid;
        float a = 0.f;
#pragma unroll
        for (int t = 0; t < 16; t++) {
            const float* gt = &sG[t * 51];
            a += __ldg(w1 +        t * 64 + w) * gt[0];
            a += __ldg(w1 + 2048 + t * 64 + w) * gt[12];
            a += __ldg(w1 + 5248 + t * 64 + w) * gt[42];
        }
        outp[w] = S.s1[0] * a;
    } else if (tid < 88) {                // c1: m3=24, k=3; p5(3072,13) p13(6272,43)
        int w = tid - 64;
        float a0 = 0.f, a1 = 0.f, a2 = 0.f;
#pragma unroll
        for (int t = 0; t < 16; t++) {
            const float* gt = &sG[t * 51];
            float wv = __ldg(w1 + 3072 + t * 24 + w);
            a0 += wv * gt[13]; a1 += wv * gt[14]; a2 += wv * gt[15];
            wv = __ldg(w1 + 6272 + t * 24 + w);
            a0 += wv * gt[43]; a1 += wv * gt[44]; a2 += wv * gt[45];
        }
        float sc = S.s1[1];
        outp[64 + w * 3 + 0] = sc * a0;
        outp[64 + w * 3 + 1] = sc * a1;
        outp[64 + w * 3 + 2] = sc * a2;
    } else if (tid < 112) {               // c2: m3=24, k=3; p1(1024,1) p3(1664,9) p7(3712,21) p10(4608,34)
        int w = tid - 88;
        float a0 = 0.f, a1 = 0.f, a2 = 0.f;
#pragma unroll
        for (int t = 0; t < 16; t++) {
            const float* gt = &sG[t * 51];
            float wv = __ldg(w1 + 1024 + t * 24 + w);
            a0 += wv * gt[1];  a1 += wv * gt[2];  a2 += wv * gt[3];
            wv = __ldg(w1 + 1664 + t * 24 + w);
            a0 += wv * gt[9];  a1 += wv * gt[10]; a2 += wv * gt[11];
            wv = __ldg(w1 + 3712 + t * 24 + w);
            a0 += wv * gt[21]; a1 += wv * gt[22]; a2 += wv * gt[23];
            wv = __ldg(w1 + 4608 + t * 24 + w);
            a0 += wv * gt[34]; a1 += wv * gt[35]; a2 += wv * gt[36];
        }
        float sc = S.s1[2];
        outp[136 + w * 3 + 0] = sc * a0;
        outp[136 + w * 3 + 1] = sc * a1;
        outp[136 + w * 3 + 2] = sc * a2;
    } else if (tid < 128) {               // c3: m3=16, k=5; p2(1408,4) p6(3456,16) p9(4352,29) p14(6656,46)
        int w = tid - 112;
        float a0 = 0.f, a1 = 0.f, a2 = 0.f, a3 = 0.f, a4 = 0.f;
#pragma unroll
        for (int t = 0; t < 16; t++) {
            const float* gt = &sG[t * 51];
            float wv = __ldg(w1 + 1408 + t * 16 + w);
            a0 += wv * gt[4];  a1 += wv * gt[5];  a2 += wv * gt[6];  a3 += wv * gt[7];  a4 += wv * gt[8];
            wv = __ldg(w1 + 3456 + t * 16 + w);
            a0 += wv * gt[16]; a1 += wv * gt[17]; a2 += wv * gt[18]; a3 += wv * gt[19]; a4 += wv * gt[20];
            wv = __ldg(w1 + 4352 + t * 16 + w);
            a0 += wv * gt[29]; a1 += wv * gt[30]; a2 += wv * gt[31]; a3 += wv * gt[32]; a4 += wv * gt[33];
            wv = __ldg(w1 + 6656 + t * 16 + w);
            a0 += wv * gt[46]; a1 += wv * gt[47]; a2 += wv * gt[48]; a3 += wv * gt[49]; a4 += wv * gt[50];
        }
        float sc = S.s1[3];
        outp[208 + w * 5 + 0] = sc * a0;
        outp[208 + w * 5 + 1] = sc * a1;
        outp[208 + w * 5 + 2] = sc * a2;
        outp[208 + w * 5 + 3] = sc * a3;
        outp[208 + w * 5 + 4] = sc * a4;
    } else {                              // c4: m3=16, k=5; p8(4096,24) p11(4992,37)
        int w = tid - 128;
        float a0 = 0.f, a1 = 0.f, a2 = 0.f, a3 = 0.f, a4 = 0.f;
#pragma unroll
        for (int t = 0; t < 16; t++) {
            const float* gt = &sG[t * 51];
            float wv = __ldg(w1 + 4096 + t * 16 + w);
            a0 += wv * gt[24]; a1 += wv * gt[25]; a2 += wv * gt[26]; a3 += wv * gt[27]; a4 += wv * gt[28];
            wv = __ldg(w1 + 4992 + t * 16 + w);
            a0 += wv * gt[37]; a1 += wv * gt[38]; a2 += wv * gt[39]; a3 += wv * gt[40]; a4 += wv * gt[41];
        }
        float sc = S.s1[4];
        outp[288 + w * 5 + 0] = sc * a0;
        outp[288 + w * 5 + 1] = sc * a1;
        outp[288 + w * 5 + 2] = sc * a2;
        outp[288 + w * 5 + 3] = sc * a3;
        outp[288 + w * 5 + 4] = sc * a4;
    }
}

// ============================================================================
// K4: TP2 + both final segment sums.  One warp per edge.
// ============================================================================
__global__ void k_tp2(const float* __restrict__ pos, const int* __restrict__ zarr,
                      const int* __restrict__ batch,
                      const int* __restrict__ esrc, const int* __restrict__ edst,
                      const float* __restrict__ w2, float* __restrict__ out,
                      int E, TP2P P) {
    int gt = blockIdx.x * blockDim.x + threadIdx.x;
    int e = gt >> 5, lane = gt & 31;
    if (e >= E) return;
    int s = __ldg(esrc + e), d = __ldg(edst + e);
    float x = __ldg(pos + 3 * s + 0) - __ldg(pos + 3 * d + 0);
    float y = __ldg(pos + 3 * s + 1) - __ldg(pos + 3 * d + 1);
    float z = __ldg(pos + 3 * s + 2) - __ldg(pos + 3 * d + 2);
    float sh[9];
    compute_sh(x, y, z, sh);
    float v1[3], v2[5];
#pragma unroll
    for (int i = 0; i < 3; i++) {
        float a = 0.f;
#pragma unroll
        for (int j = 0; j < 3; j++) a += sh[1 + j] * P.c110[i * 3 + j];
        v1[i] = a;
    }
#pragma unroll
    for (int i = 0; i < 5; i++) {
        float a = 0.f;
#pragma unroll
        for (int j = 0; j < 5; j++) a += sh[4 + j] * P.c220[i * 5 + j];
        v2[i] = a;
    }
    float v0 = P.c000;  // sh[0] == 1
    int t = 4 * __ldg(zarr + s) + __ldg(zarr + d);
    const float* mid = &g_node_mid[(size_t)s * MIDW];

    float acc0 = 0.f;
    float acc[6] = {0.f, 0.f, 0.f, 0.f, 0.f, 0.f};

    // 144 "u-rows": [0,64) q0 | [64,88) q1 | [88,112) q2 | [112,128) q3 | [128,144) q4
    for (int r = lane; r < 144; r += 32) {
        if (r < 64) {            // q0: mid[0..64), l=0, m3=6, W off 0, u-stride 96
            float dq = mid[r] * v0;
            const float* Wp = &w2[r * 96 + t * 6];
#pragma unroll
            for (int w = 0; w < 6; w++) acc[w] += dq * __ldg(Wp + w);
        } else if (r < 88) {     // q1: mid[64..136), l=1, m3=1, W off 6144
            int u = r - 64;
            const float* m0 = &mid[64 + u * 3];
            float dq = m0[0] * v1[0] + m0[1] * v1[1] + m0[2] * v1[2];
            acc0 += dq * __ldg(w2 + 6144 + u * 16 + t);
        } else if (r < 112) {    // q2: mid[136..208), l=1, m3=6, W off 6528
            int u = r - 88;
            const float* m0 = &mid[136 + u * 3];
            float dq = m0[0] * v1[0] + m0[1] * v1[1] + m0[2] * v1[2];
            const float* Wp = &w2[6528 + u * 96 + t * 6];
#pragma unroll
            for (int w = 0; w < 6; w++) acc[w] += dq * __ldg(Wp + w);
        } else if (r < 128) {    // q3: mid[208..288), l=2, m3=6, W off 8832
            int u = r - 112;
            const float* m0 = &mid[208 + u * 5];
            float dq = m0[0] * v2[0] + m0[1] * v2[1] + m0[2] * v2[2] + m0[3] * v2[3] + m0[4] * v2[4];
            const float* Wp = &w2[8832 + u * 96 + t * 6];
#pragma unroll
            for (int w = 0; w < 6; w++) acc[w] += dq * __ldg(Wp + w);
        } else {                 // q4: mid[288..368), l=2, m3=1, W off 10368
            int u = r - 128;
            const float* m0 = &mid[288 + u * 5];
            float dq = m0[0] * v2[0] + m0[1] * v2[1] + m0[2] * v2[2] + m0[3] * v2[3] + m0[4] * v2[4];
            acc0 += dq * __ldg(w2 + 10368 + u * 16 + t);
        }
    }

#pragma unroll
    for (int o = 16; o > 0; o >>= 1) {
        acc0 += __shfl_down_sync(0xffffffffu, acc0, o);
#pragma unroll
        for (int w = 0; w < 6; w++) acc[w] += __shfl_down_sync(0xffffffffu, acc[w], o);
    }
    if (lane == 0) {
        int g = __ldg(batch + d);
        float* og = &out[(size_t)g * 7];
        atomicAdd(og + 0, P.s20 * acc0);
#pragma unroll
        for (int w = 0; w < 6; w++) atomicAdd(og + 1 + w, P.s21 * acc[w]);
    }
}

// ============================================================================
// Host: Wigner 3j computation (exactly mirrors the reference _cg/_u/_w3j)
// ============================================================================
static double hfact(int n) { double r = 1.0; for (int i = 2; i <= n; i++) r *= (double)i; return r; }

static double hcg(int j1, int j2, int j3, int m1, int m2, int m3) {
    if (m1 + m2 != m3) return 0.0;
    double pre = sqrt((2.0 * j3 + 1.0) * hfact(j3 + j1 - j2) * hfact(j3 - j1 + j2) *
                      hfact(j1 + j2 - j3) / hfact(j1 + j2 + j3 + 1));
    pre *= sqrt(hfact(j3 + m3) * hfact(j3 - m3) * hfact(j1 - m1) * hfact(j1 + m1) *
                hfact(j2 - m2) * hfact(j2 + m2));
    int kmin = 0;
    if (j2 - j3 - m1 > kmin) kmin = j2 - j3 - m1;
    if (j1 - j3 + m2 > kmin) kmin = j1 - j3 + m2;
    int kmax = j1 + j2 - j3;
    if (j1 - m1 < kmax) kmax = j1 - m1;
    if (j2 + m2 < kmax) kmax = j2 + m2;
    double s = 0.0;
    for (int k = kmin; k <= kmax; k++) {
        double den = hfact(k) * hfact(j1 + j2 - j3 - k) * hfact(j1 - m1 - k) *
                     hfact(j2 + m2 - k) * hfact(j3 - j2 + m1 + k) * hfact(j3 - j1 - m2 + k);
        s += ((k & 1) ? -1.0 : 1.0) / den;
    }
    return pre * s;
}

static void humat(int l, double Ur[5][5], double Ui[5][5]) {
    for (int a = 0; a < 5; a++) for (int b = 0; b < 5; b++) { Ur[a][b] = 0.0; Ui[a][b] = 0.0; }
    double is2 = 1.0 / sqrt(2.0);
    for (int m = -l; m <= l; m++) {
        int r = m + l;
        if (m > 0) {
            Ur[r][l - m] = is2;
            Ur[r][l + m] = ((m & 1) ? -1.0 : 1.0) * is2;
        } else if (m == 0) {
            Ur[l][l] = 1.0;
        } else {
            Ui[r][l + m] = is2;
            Ui[r][l - m] = -(((-m) & 1) ? -1.0 : 1.0) * is2;
        }
    }
}

static void hw3j(int l1, int l2, int l3, float* out) {
    int n1 = 2 * l1 + 1, n2 = 2 * l2 + 1, n3 = 2 * l3 + 1;
    double C[5][5][5];
    memset(C, 0, sizeof(C));
    for (int m1 = -l1; m1 <= l1; m1++)
        for (int m2 = -l2; m2 <= l2; m2++) {
            int m3 = m1 + m2;
            if (m3 < -l3 || m3 > l3) continue;
            C[m1 + l1][m2 + l2][m3 + l3] = hcg(l1, l2, l3, m1, m2, m3);
        }
    double U1r[5][5], U1i[5][5], U2r[5][5], U2i[5][5], U3r[5][5], U3i[5][5];
    humat(l1, U1r, U1i); humat(l2, U2r, U2i); humat(l3, U3r, U3i);
    double Tre[5][5][5], Tim[5][5][5];
    double maxr = 0.0, maxi = 0.0;
    for (int a = 0; a < n1; a++)
        for (int b = 0; b < n2; b++)
            for (int c = 0; c < n3; c++) {
                double sr = 0.0, si = 0.0;
                for (int m = 0; m < n1; m++)
                    for (int n = 0; n < n2; n++)
                        for (int o = 0; o < n3; o++) {
                            double cv = C[m][n][o];
                            if (cv == 0.0) continue;
                            double ar = U1r[a][m], ai = U1i[a][m];
                            double br = U2r[b][n], bi = U2i[b][n];
                            double qr = ar * br - ai * bi, qi = ar * bi + ai * br;
                            double cr = U3r[c][o], ci = -U3i[c][o];
                            double rr = qr * cr - qi * ci, ri = qr * ci + qi * cr;
                            sr += rr * cv; si += ri * cv;
                        }
                Tre[a][b][c] = sr; Tim[a][b][c] = si;
                if (fabs(sr) > maxr) maxr = fabs(sr);
                if (fabs(si) > maxi) maxi = fabs(si);
            }
    bool useR = (maxr >= maxi);
    double nrm = 0.0;
    for (int a = 0; a < n1; a++)
        for (int b = 0; b < n2; b++)
            for (int c = 0; c < n3; c++) {
                double v = useR ? Tre[a][b][c] : Tim[a][b][c];
                nrm += v * v;
            }
    nrm = sqrt(nrm);
    for (int a = 0; a < n1; a++)
        for (int b = 0; b < n2; b++)
            for (int c = 0; c < n3; c++) {
                double v = useR ? Tre[a][b][c] : Tim[a][b][c];
                out[(a * n2 + b) * n3 + c] = (float)(v / nrm);
            }
}

// ============================================================================
// kernel_launch
// ============================================================================
extern "C" void kernel_launch(void* const* d_in, const int* in_sizes, int n_in,
                              void* d_out, int out_size) {
    const float* pos   = (const float*)d_in[0];
    const int*   zarr  = (const int*)  d_in[1];
    const int*   batch = (const int*)  d_in[2];
    const int*   esrc  = (const int*)  d_in[3];
    const int*   edst  = (const int*)  d_in[4];
    const float* w1    = (const float*)d_in[5];
    const float* w2    = (const float*)d_in[6];
    float*       out   = (float*)d_out;
    int E = in_sizes[3];

    // Host precompute (runs once at capture time; graph replays skip it)
    W3JP P;
    hw3j(0, 0, 0, &P.c000);
    hw3j(0, 1, 1, P.c011);  hw3j(0, 2, 2, P.c022);
    hw3j(1, 0, 1, P.c101);  hw3j(1, 1, 0, P.c110);
    hw3j(1, 1, 1, P.c111);  hw3j(1, 1, 2, P.c112);
    hw3j(1, 2, 1, P.c121);  hw3j(1, 2, 2, P.c122);
    hw3j(2, 0, 2, P.c202);  hw3j(2, 1, 1, P.c211);  hw3j(2, 1, 2, P.c212);
    hw3j(2, 2, 0, P.c220);  hw3j(2, 2, 1, P.c221);  hw3j(2, 2, 2, P.c222);

    S1P S1;
    {
        const double fan1[5] = {48.0, 32.0, 64.0, 64.0, 32.0};
        const int l3c[5] = {0, 1, 1, 2, 2};
        for (int c = 0; c < 5; c++)
            S1.s1[c] = (float)(4.0 * sqrt(2.0 * l3c[c] + 1.0) / sqrt(fan1[c]) / 3.0);
    }

    TP2P P2;
    memcpy(P2.c110, P.c110, sizeof(P2.c110));
    memcpy(P2.c220, P.c220, sizeof(P2.c220));
    P2.c000 = P.c000;
    P2.s20 = (float)(2.0 / (sqrt(3.0) * sqrt(640.0)));
    P2.s21 = (float)(2.0 / (sqrt(3.0) * sqrt(1664.0)));

    // K0: zero scratch + output
    k_zero<<<4096, 256>>>(out, out_size);
    // K1: SH accumulation into node_sh
    k_sh<<<(E + 255) / 256, 256>>>(pos, esrc, edst, E);
    // K2: TP1 geometric accumulation into G
    k_tp1<<<(E + 255) / 256, 256>>>(pos, zarr, esrc, edst, E, P);
    // K3: dense node transform -> node_mid
    k_mid<<<NN, 160>>>(w1, S1);
    // K4: TP2 + graph reduction -> out
    {
        long long threads = (long long)E * 32;
        int blocks = (int)((threads + 255) / 256);
        k_tp2<<<blocks, 256>>>(pos, zarr, batch, esrc, edst, w2, out, E, P2);
    }
}

// round 5
// speedup vs baseline: 3.1200x; 3.1200x over previous
#include <cuda_runtime.h>
#include <cuda_bf16.h>
#include <math.h>
#include <string.h>

// ============================================================================
// Problem constants (fixed by the dataset)
// ============================================================================
#define NN    20000          // nodes
#define NGR   5000           // graphs
#define MIDW  368            // dim of IR_MID
#define GROW  204            // 4 * 51 per-node G row (indexed by z[src])
#define QROW  64             // padded 62-float Q row per (src, z_dst)

// ============================================================================
// Device scratch (static — no allocation allowed)
// ============================================================================
__device__ float4 g_G4[(size_t)NN * GROW / 4];      // 16.3 MB geometric accumulators
__device__ float  g_node_sh[(size_t)NN * 9];        // raw SH sums per node
__device__ float  g_Q[(size_t)NN * 4 * QROW];       // 20.5 MB W2-contracted tables

// ============================================================================
// Parameter structs (filled on host at capture time, passed by value)
// ============================================================================
struct W3JP {
    float c000;
    float c011[9],  c022[25], c101[9],  c110[9];
    float c111[27], c112[45], c121[45], c122[75];
    float c202[25], c211[45], c212[75];
    float c220[25], c221[75], c222[125];
};
struct TP2P  { float c110[9]; float c220[25]; };
struct MIDQP { float s1[5]; float s20, s21, q0s; };   // q0s = c000 * s21

// ============================================================================
// Device helpers
// ============================================================================
__device__ __forceinline__ void compute_sh(float x, float y, float z, float sh[9]) {
    const float s3  = 1.7320508075688772f;
    const float s15 = 3.8729833462074170f;
    const float s5  = 2.2360679774997896f;
    float r2 = x * x + y * y + z * z;
    sh[0] = 1.0f;
    sh[1] = s3 * y; sh[2] = s3 * z; sh[3] = s3 * x;
    sh[4] = s15 * x * y;
    sh[5] = s15 * y * z;
    sh[6] = 0.5f * s5 * (3.0f * z * z - r2);
    sh[7] = s15 * x * z;
    sh[8] = 0.5f * s15 * (x * x - y * y);
}

// ============================================================================
// K0: zero scratch + output
// ============================================================================
__global__ void k_zero(float* __restrict__ out, int outN) {
    size_t idx    = (size_t)blockIdx.x * blockDim.x + threadIdx.x;
    size_t stride = (size_t)gridDim.x * blockDim.x;
    const float4 z4 = make_float4(0.f, 0.f, 0.f, 0.f);
    const size_t ng4 = (size_t)NN * GROW / 4;
    for (size_t j = idx; j < ng4; j += stride) g_G4[j] = z4;
    for (size_t j = idx; j < (size_t)NN * 9; j += stride) g_node_sh[j] = 0.f;
    for (size_t j = idx; j < (size_t)outN; j += stride) out[j] = 0.f;
}

// ============================================================================
// K1: per-edge SH -> atomic accumulate into node_sh[dst] (raw, unscaled)
// ============================================================================
__global__ void k_sh(const float* __restrict__ pos,
                     const int* __restrict__ esrc, const int* __restrict__ edst, int E) {
    int e = blockIdx.x * blockDim.x + threadIdx.x;
    if (e >= E) return;
    int s = __ldg(esrc + e), d = __ldg(edst + e);
    float x = __ldg(pos + 3 * s + 0) - __ldg(pos + 3 * d + 0);
    float y = __ldg(pos + 3 * s + 1) - __ldg(pos + 3 * d + 1);
    float z = __ldg(pos + 3 * s + 2) - __ldg(pos + 3 * d + 2);
    float sh[9];
    compute_sh(x, y, z, sh);
    float* np = &g_node_sh[(size_t)d * 9];
#pragma unroll
    for (int i = 0; i < 9; i++) atomicAdd(np + i, sh[i]);
}

// ============================================================================
// K2: per-edge TP1 geometry -> 51 atomics into G[dst][z_src]
// ============================================================================
__global__ void k_tp1(const float* __restrict__ pos, const int* __restrict__ zarr,
                      const int* __restrict__ esrc, const int* __restrict__ edst,
                      int E, W3JP P) {
    int e = blockIdx.x * blockDim.x + threadIdx.x;
    if (e >= E) return;
    int s = __ldg(esrc + e), d = __ldg(edst + e);
    float x = __ldg(pos + 3 * s + 0) - __ldg(pos + 3 * d + 0);
    float y = __ldg(pos + 3 * s + 1) - __ldg(pos + 3 * d + 1);
    float z = __ldg(pos + 3 * s + 2) - __ldg(pos + 3 * d + 2);
    float sh[9];
    compute_sh(x, y, z, sh);
    float xa[9];
    const float* ns = &g_node_sh[(size_t)s * 9];
#pragma unroll
    for (int i = 0; i < 9; i++) xa[i] = ns[i];
    int zs = __ldg(zarr + s);

    float g[51];
#pragma unroll
    for (int m = 0; m < 51; m++) g[m] = 0.f;

    float xa0 = xa[0];
    g[0] = xa0 * P.c000;                       // p0 (0,0,0); sh[0]==1
#pragma unroll
    for (int j = 0; j < 3; j++) {              // p1 (0,1,1) -> 1
        float f = xa0 * sh[1 + j];
#pragma unroll
        for (int k = 0; k < 3; k++) g[1 + k] += f * P.c011[j * 3 + k];
    }
#pragma unroll
    for (int j = 0; j < 5; j++) {              // p2 (0,2,2) -> 4
        float f = xa0 * sh[4 + j];
#pragma unroll
        for (int k = 0; k < 5; k++) g[4 + k] += f * P.c022[j * 5 + k];
    }
#pragma unroll
    for (int i = 0; i < 3; i++) {              // p3 (1,0,1) -> 9
        float f = xa[1 + i];
#pragma unroll
        for (int k = 0; k < 3; k++) g[9 + k] += f * P.c101[i * 3 + k];
    }
#pragma unroll
    for (int i = 0; i < 3; i++) {              // p4->12, p5->13, p6->16
#pragma unroll
        for (int j = 0; j < 3; j++) {
            float f = xa[1 + i] * sh[1 + j];
            g[12] += f * P.c110[i * 3 + j];
#pragma unroll
            for (int k = 0; k < 3; k++) g[13 + k] += f * P.c111[(i * 3 + j) * 3 + k];
#pragma unroll
            for (int k = 0; k < 5; k++) g[16 + k] += f * P.c112[(i * 3 + j) * 5 + k];
        }
    }
#pragma unroll
    for (int i = 0; i < 3; i++) {              // p7->21, p8->24
#pragma unroll
        for (int j = 0; j < 5; j++) {
            float f = xa[1 + i] * sh[4 + j];
#pragma unroll
            for (int k = 0; k < 3; k++) g[21 + k] += f * P.c121[(i * 5 + j) * 3 + k];
#pragma unroll
            for (int k = 0; k < 5; k++) g[24 + k] += f * P.c122[(i * 5 + j) * 5 + k];
        }
    }
#pragma unroll
    for (int i = 0; i < 5; i++) {              // p9 -> 29
        float f = xa[4 + i];
#pragma unroll
        for (int k = 0; k < 5; k++) g[29 + k] += f * P.c202[i * 5 + k];
    }
#pragma unroll
    for (int i = 0; i < 5; i++) {              // p10->34, p11->37
#pragma unroll
        for (int j = 0; j < 3; j++) {
            float f = xa[4 + i] * sh[1 + j];
#pragma unroll
            for (int k = 0; k < 3; k++) g[34 + k] += f * P.c211[(i * 3 + j) * 3 + k];
#pragma unroll
            for (int k = 0; k < 5; k++) g[37 + k] += f * P.c212[(i * 3 + j) * 5 + k];
        }
    }
#pragma unroll
    for (int i = 0; i < 5; i++) {              // p12->42, p13->43, p14->46
#pragma unroll
        for (int j = 0; j < 5; j++) {
            float f = xa[4 + i] * sh[4 + j];
            g[42] += f * P.c220[i * 5 + j];
#pragma unroll
            for (int k = 0; k < 3; k++) g[43 + k] += f * P.c221[(i * 5 + j) * 3 + k];
#pragma unroll
            for (int k = 0; k < 5; k++) g[46 + k] += f * P.c222[(i * 5 + j) * 5 + k];
        }
    }

    float* Gf = reinterpret_cast<float*>(g_G4);
    float* Gp = &Gf[((size_t)d * 4 + zs) * 51];
#pragma unroll
    for (int m = 0; m < 51; m++) atomicAdd(Gp + m, g[m]);
}

// ============================================================================
// K3 (fused): per-node TP1 dense transform (-> smem mid) then TP2 W2
//             contraction -> Q[n][zd][62]. One block (256 thr) per node.
//
// Stage 1 thread map: [0,64) c0 | [64,88) c1 | [88,112) c2 | [112,128) c3 | [128,144) c4
// Stage 2 thread map: tid = zd*62 + slot for tid<248; 248..255 write pads.
// ============================================================================
__global__ void k_midq(const float* __restrict__ w1, const float* __restrict__ w2,
                       const int* __restrict__ zarr, MIDQP M) {
    __shared__ float sG[GROW];
    __shared__ float sMid[MIDW];
    int n = blockIdx.x;
    int tid = threadIdx.x;
    const float* Gf = reinterpret_cast<const float*>(g_G4);
    for (int i = tid; i < GROW; i += blockDim.x) sG[i] = Gf[(size_t)n * GROW + i];
    __syncthreads();

    int zn = __ldg(zarr + n);

    // ---------------- Stage 1: mid = W1-transform of G ----------------
    if (tid < 144) {
        if (tid < 64) {                       // c0: p0(0,g0) p4(2048,12) p12(5248,42)
            int w = tid;
            float a = 0.f;
#pragma unroll
            for (int g = 0; g < 4; g++) {
                int t = 4 * g + zn;
                const float* gt = &sG[g * 51];
                a += __ldg(w1 +        t * 64 + w) * gt[0];
                a += __ldg(w1 + 2048 + t * 64 + w) * gt[12];
                a += __ldg(w1 + 5248 + t * 64 + w) * gt[42];
            }
            sMid[w] = M.s1[0] * a;
        } else if (tid < 88) {                // c1: p5(3072,13) p13(6272,43)
            int w = tid - 64;
            float a0 = 0.f, a1 = 0.f, a2 = 0.f;
#pragma unroll
            for (int g = 0; g < 4; g++) {
                int t = 4 * g + zn;
                const float* gt = &sG[g * 51];
                float wv = __ldg(w1 + 3072 + t * 24 + w);
                a0 += wv * gt[13]; a1 += wv * gt[14]; a2 += wv * gt[15];
                wv = __ldg(w1 + 6272 + t * 24 + w);
                a0 += wv * gt[43]; a1 += wv * gt[44]; a2 += wv * gt[45];
            }
            float sc = M.s1[1];
            sMid[64 + w * 3 + 0] = sc * a0;
            sMid[64 + w * 3 + 1] = sc * a1;
            sMid[64 + w * 3 + 2] = sc * a2;
        } else if (tid < 112) {               // c2: p1(1024,1) p3(1664,9) p7(3712,21) p10(4608,34)
            int w = tid - 88;
            float a0 = 0.f, a1 = 0.f, a2 = 0.f;
#pragma unroll
            for (int g = 0; g < 4; g++) {
                int t = 4 * g + zn;
                const float* gt = &sG[g * 51];
                float wv = __ldg(w1 + 1024 + t * 24 + w);
                a0 += wv * gt[1];  a1 += wv * gt[2];  a2 += wv * gt[3];
                wv = __ldg(w1 + 1664 + t * 24 + w);
                a0 += wv * gt[9];  a1 += wv * gt[10]; a2 += wv * gt[11];
                wv = __ldg(w1 + 3712 + t * 24 + w);
                a0 += wv * gt[21]; a1 += wv * gt[22]; a2 += wv * gt[23];
                wv = __ldg(w1 + 4608 + t * 24 + w);
                a0 += wv * gt[34]; a1 += wv * gt[35]; a2 += wv * gt[36];
            }
            float sc = M.s1[2];
            sMid[136 + w * 3 + 0] = sc * a0;
            sMid[136 + w * 3 + 1] = sc * a1;
            sMid[136 + w * 3 + 2] = sc * a2;
        } else if (tid < 128) {               // c3: p2(1408,4) p6(3456,16) p9(4352,29) p14(6656,46)
            int w = tid - 112;
            float a0 = 0.f, a1 = 0.f, a2 = 0.f, a3 = 0.f, a4 = 0.f;
#pragma unroll
            for (int g = 0; g < 4; g++) {
                int t = 4 * g + zn;
                const float* gt = &sG[g * 51];
                float wv = __ldg(w1 + 1408 + t * 16 + w);
                a0 += wv * gt[4];  a1 += wv * gt[5];  a2 += wv * gt[6];  a3 += wv * gt[7];  a4 += wv * gt[8];
                wv = __ldg(w1 + 3456 + t * 16 + w);
                a0 += wv * gt[16]; a1 += wv * gt[17]; a2 += wv * gt[18]; a3 += wv * gt[19]; a4 += wv * gt[20];
                wv = __ldg(w1 + 4352 + t * 16 + w);
                a0 += wv * gt[29]; a1 += wv * gt[30]; a2 += wv * gt[31]; a3 += wv * gt[32]; a4 += wv * gt[33];
                wv = __ldg(w1 + 6656 + t * 16 + w);
                a0 += wv * gt[46]; a1 += wv * gt[47]; a2 += wv * gt[48]; a3 += wv * gt[49]; a4 += wv * gt[50];
            }
            float sc = M.s1[3];
            sMid[208 + w * 5 + 0] = sc * a0;
            sMid[208 + w * 5 + 1] = sc * a1;
            sMid[208 + w * 5 + 2] = sc * a2;
            sMid[208 + w * 5 + 3] = sc * a3;
            sMid[208 + w * 5 + 4] = sc * a4;
        } else {                              // c4: p8(4096,24) p11(4992,37)
            int w = tid - 128;
            float a0 = 0.f, a1 = 0.f, a2 = 0.f, a3 = 0.f, a4 = 0.f;
#pragma unroll
            for (int g = 0; g < 4; g++) {
                int t = 4 * g + zn;
                const float* gt = &sG[g * 51];
                float wv = __ldg(w1 + 4096 + t * 16 + w);
                a0 += wv * gt[24]; a1 += wv * gt[25]; a2 += wv * gt[26]; a3 += wv * gt[27]; a4 += wv * gt[28];
                wv = __ldg(w1 + 4992 + t * 16 + w);
                a0 += wv * gt[37]; a1 += wv * gt[38]; a2 += wv * gt[39]; a3 += wv * gt[40]; a4 += wv * gt[41];
            }
            float sc = M.s1[4];
            sMid[288 + w * 5 + 0] = sc * a0;
            sMid[288 + w * 5 + 1] = sc * a1;
            sMid[288 + w * 5 + 2] = sc * a2;
            sMid[288 + w * 5 + 3] = sc * a3;
            sMid[288 + w * 5 + 4] = sc * a4;
        }
    }
    __syncthreads();

    // ---------------- Stage 2: Q[n][zd][slot] ----------------
    float* Qn = &g_Q[(size_t)n * 4 * QROW];
    if (tid < 248) {
        int zd = tid / 62, slot = tid - zd * 62;
        int t = 4 * zn + zd;                  // node n is the SRC for TP2
        float val;
        if (slot < 6) {                       // Q0[w] : u<64, mid[0..64)
            int w = slot;
            float a = 0.f;
#pragma unroll 8
            for (int u = 0; u < 64; u++) a += sMid[u] * __ldg(w2 + u * 96 + t * 6 + w);
            val = M.q0s * a;
        } else if (slot < 9) {                // A1[i] : u<24, mid[64+u*3+i]
            int i = slot - 6;
            float a = 0.f;
#pragma unroll
            for (int u = 0; u < 24; u++) a += sMid[64 + u * 3 + i] * __ldg(w2 + 6144 + u * 16 + t);
            val = M.s20 * a;
        } else if (slot < 27) {               // B1[i][w] : u<24, mid[136+u*3+i]
            int r = slot - 9, i = r / 6, w = r - i * 6;
            float a = 0.f;
#pragma unroll
            for (int u = 0; u < 24; u++) a += sMid[136 + u * 3 + i] * __ldg(w2 + 6528 + u * 96 + t * 6 + w);
            val = M.s21 * a;
        } else if (slot < 32) {               // A2[i] : u<16, mid[288+u*5+i]
            int i = slot - 27;
            float a = 0.f;
#pragma unroll
            for (int u = 0; u < 16; u++) a += sMid[288 + u * 5 + i] * __ldg(w2 + 10368 + u * 16 + t);
            val = M.s20 * a;
        } else {                              // B2[i][w] : u<16, mid[208+u*5+i]
            int r = slot - 32, i = r / 6, w = r - i * 6;
            float a = 0.f;
#pragma unroll
            for (int u = 0; u < 16; u++) a += sMid[208 + u * 5 + i] * __ldg(w2 + 8832 + u * 96 + t * 6 + w);
            val = M.s21 * a;
        }
        Qn[zd * QROW + slot] = val;
    } else {
        int r = tid - 248;                    // 8 threads -> 4 zd x 2 pad slots
        int zd = r >> 1, pad = 62 + (r & 1);
        Qn[zd * QROW + pad] = 0.f;
    }
}

// ============================================================================
// K4: per-edge TP2 via Q table + final graph reduction. One THREAD per edge.
//     acc0  = sum_i v1[i]*q[6+i]      + sum_i v2[i]*q[27+i]
//     acc_w = q[w] + sum_i v1[i]*q[9+i*6+w] + sum_i v2[i]*q[32+i*6+w]
// ============================================================================
__global__ void k_tp2(const float* __restrict__ pos, const int* __restrict__ zarr,
                      const int* __restrict__ batch,
                      const int* __restrict__ esrc, const int* __restrict__ edst,
                      float* __restrict__ out, int E, TP2P P) {
    int e = blockIdx.x * blockDim.x + threadIdx.x;
    if (e >= E) return;
    int s = __ldg(esrc + e), d = __ldg(edst + e);
    float x = __ldg(pos + 3 * s + 0) - __ldg(pos + 3 * d + 0);
    float y = __ldg(pos + 3 * s + 1) - __ldg(pos + 3 * d + 1);
    float z = __ldg(pos + 3 * s + 2) - __ldg(pos + 3 * d + 2);
    float sh[9];
    compute_sh(x, y, z, sh);
    float v1[3], v2[5];
#pragma unroll
    for (int i = 0; i < 3; i++) {
        float a = 0.f;
#pragma unroll
        for (int j = 0; j < 3; j++) a += sh[1 + j] * P.c110[i * 3 + j];
        v1[i] = a;
    }
#pragma unroll
    for (int i = 0; i < 5; i++) {
        float a = 0.f;
#pragma unroll
        for (int j = 0; j < 5; j++) a += sh[4 + j] * P.c220[i * 5 + j];
        v2[i] = a;
    }
    int zd = __ldg(zarr + d);
    const float* q = &g_Q[((size_t)s * 4 + zd) * QROW];

    float acc0 = 0.f;
    float accw[6];
#pragma unroll
    for (int w = 0; w < 6; w++) accw[w] = __ldg(q + w);   // v0-folded constant term
#pragma unroll
    for (int i = 0; i < 3; i++) {
        float v = v1[i];
        acc0 += v * __ldg(q + 6 + i);
#pragma unroll
        for (int w = 0; w < 6; w++) accw[w] += v * __ldg(q + 9 + i * 6 + w);
    }
#pragma unroll
    for (int i = 0; i < 5; i++) {
        float v = v2[i];
        acc0 += v * __ldg(q + 27 + i);
#pragma unroll
        for (int w = 0; w < 6; w++) accw[w] += v * __ldg(q + 32 + i * 6 + w);
    }

    int g = __ldg(batch + d);
    float* og = &out[(size_t)g * 7];
    atomicAdd(og + 0, acc0);
#pragma unroll
    for (int w = 0; w < 6; w++) atomicAdd(og + 1 + w, accw[w]);
}

// ============================================================================
// Host: Wigner 3j computation (exactly mirrors the reference _cg/_u/_w3j)
// ============================================================================
static double hfact(int n) { double r = 1.0; for (int i = 2; i <= n; i++) r *= (double)i; return r; }

static double hcg(int j1, int j2, int j3, int m1, int m2, int m3) {
    if (m1 + m2 != m3) return 0.0;
    double pre = sqrt((2.0 * j3 + 1.0) * hfact(j3 + j1 - j2) * hfact(j3 - j1 + j2) *
                      hfact(j1 + j2 - j3) / hfact(j1 + j2 + j3 + 1));
    pre *= sqrt(hfact(j3 + m3) * hfact(j3 - m3) * hfact(j1 - m1) * hfact(j1 + m1) *
                hfact(j2 - m2) * hfact(j2 + m2));
    int kmin = 0;
    if (j2 - j3 - m1 > kmin) kmin = j2 - j3 - m1;
    if (j1 - j3 + m2 > kmin) kmin = j1 - j3 + m2;
    int kmax = j1 + j2 - j3;
    if (j1 - m1 < kmax) kmax = j1 - m1;
    if (j2 + m2 < kmax) kmax = j2 + m2;
    double s = 0.0;
    for (int k = kmin; k <= kmax; k++) {
        double den = hfact(k) * hfact(j1 + j2 - j3 - k) * hfact(j1 - m1 - k) *
                     hfact(j2 + m2 - k) * hfact(j3 - j2 + m1 + k) * hfact(j3 - j1 - m2 + k);
        s += ((k & 1) ? -1.0 : 1.0) / den;
    }
    return pre * s;
}

static void humat(int l, double Ur[5][5], double Ui[5][5]) {
    for (int a = 0; a < 5; a++) for (int b = 0; b < 5; b++) { Ur[a][b] = 0.0; Ui[a][b] = 0.0; }
    double is2 = 1.0 / sqrt(2.0);
    for (int m = -l; m <= l; m++) {
        int r = m + l;
        if (m > 0) {
            Ur[r][l - m] = is2;
            Ur[r][l + m] = ((m & 1) ? -1.0 : 1.0) * is2;
        } else if (m == 0) {
            Ur[l][l] = 1.0;
        } else {
            Ui[r][l + m] = is2;
            Ui[r][l - m] = -(((-m) & 1) ? -1.0 : 1.0) * is2;
        }
    }
}

static void hw3j(int l1, int l2, int l3, float* out) {
    int n1 = 2 * l1 + 1, n2 = 2 * l2 + 1, n3 = 2 * l3 + 1;
    double C[5][5][5];
    memset(C, 0, sizeof(C));
    for (int m1 = -l1; m1 <= l1; m1++)
        for (int m2 = -l2; m2 <= l2; m2++) {
            int m3 = m1 + m2;
            if (m3 < -l3 || m3 > l3) continue;
            C[m1 + l1][m2 + l2][m3 + l3] = hcg(l1, l2, l3, m1, m2, m3);
        }
    double U1r[5][5], U1i[5][5], U2r[5][5], U2i[5][5], U3r[5][5], U3i[5][5];
    humat(l1, U1r, U1i); humat(l2, U2r, U2i); humat(l3, U3r, U3i);
    double Tre[5][5][5], Tim[5][5][5];
    double maxr = 0.0, maxi = 0.0;
    for (int a = 0; a < n1; a++)
        for (int b = 0; b < n2; b++)
            for (int c = 0; c < n3; c++) {
                double sr = 0.0, si = 0.0;
                for (int m = 0; m < n1; m++)
                    for (int n = 0; n < n2; n++)
                        for (int o = 0; o < n3; o++) {
                            double cv = C[m][n][o];
                            if (cv == 0.0) continue;
                            double ar = U1r[a][m], ai = U1i[a][m];
                            double br = U2r[b][n], bi = U2i[b][n];
                            double qr = ar * br - ai * bi, qi = ar * bi + ai * br;
                            double cr = U3r[c][o], ci = -U3i[c][o];
                            double rr = qr * cr - qi * ci, ri = qr * ci + qi * cr;
                            sr += rr * cv; si += ri * cv;
                        }
                Tre[a][b][c] = sr; Tim[a][b][c] = si;
                if (fabs(sr) > maxr) maxr = fabs(sr);
                if (fabs(si) > maxi) maxi = fabs(si);
            }
    bool useR = (maxr >= maxi);
    double nrm = 0.0;
    for (int a = 0; a < n1; a++)
        for (int b = 0; b < n2; b++)
            for (int c = 0; c < n3; c++) {
                double v = useR ? Tre[a][b][c] : Tim[a][b][c];
                nrm += v * v;
            }
    nrm = sqrt(nrm);
    for (int a = 0; a < n1; a++)
        for (int b = 0; b < n2; b++)
            for (int c = 0; c < n3; c++) {
                double v = useR ? Tre[a][b][c] : Tim[a][b][c];
                out[(a * n2 + b) * n3 + c] = (float)(v / nrm);
            }
}

// ============================================================================
// kernel_launch
// ============================================================================
extern "C" void kernel_launch(void* const* d_in, const int* in_sizes, int n_in,
                              void* d_out, int out_size) {
    const float* pos   = (const float*)d_in[0];
    const int*   zarr  = (const int*)  d_in[1];
    const int*   batch = (const int*)  d_in[2];
    const int*   esrc  = (const int*)  d_in[3];
    const int*   edst  = (const int*)  d_in[4];
    const float* w1    = (const float*)d_in[5];
    const float* w2    = (const float*)d_in[6];
    float*       out   = (float*)d_out;
    int E = in_sizes[3];

    // Host precompute (runs once at capture time; graph replays skip it)
    W3JP P;
    hw3j(0, 0, 0, &P.c000);
    hw3j(0, 1, 1, P.c011);  hw3j(0, 2, 2, P.c022);
    hw3j(1, 0, 1, P.c101);  hw3j(1, 1, 0, P.c110);
    hw3j(1, 1, 1, P.c111);  hw3j(1, 1, 2, P.c112);
    hw3j(1, 2, 1, P.c121);  hw3j(1, 2, 2, P.c122);
    hw3j(2, 0, 2, P.c202);  hw3j(2, 1, 1, P.c211);  hw3j(2, 1, 2, P.c212);
    hw3j(2, 2, 0, P.c220);  hw3j(2, 2, 1, P.c221);  hw3j(2, 2, 2, P.c222);

    MIDQP M;
    {
        const double fan1[5] = {48.0, 32.0, 64.0, 64.0, 32.0};
        const int l3c[5] = {0, 1, 1, 2, 2};
        for (int c = 0; c < 5; c++)
            M.s1[c] = (float)(4.0 * sqrt(2.0 * l3c[c] + 1.0) / sqrt(fan1[c]) / 3.0);
        M.s20 = (float)(2.0 / (sqrt(3.0) * sqrt(640.0)));
        M.s21 = (float)(2.0 / (sqrt(3.0) * sqrt(1664.0)));
        M.q0s = P.c000 * M.s21;
    }

    TP2P P2;
    memcpy(P2.c110, P.c110, sizeof(P2.c110));
    memcpy(P2.c220, P.c220, sizeof(P2.c220));

    // K0: zero scratch + output
    k_zero<<<2048, 256>>>(out, out_size);
    // K1: SH accumulation into node_sh
    k_sh<<<(E + 255) / 256, 256>>>(pos, esrc, edst, E);
    // K2: TP1 geometric accumulation into G[dst][z_src]
    k_tp1<<<(E + 255) / 256, 256>>>(pos, zarr, esrc, edst, E, P);
    // K3: fused dense node transform + W2 contraction -> Q
    k_midq<<<NN, 256>>>(w1, w2, zarr, M);
    // K4: per-edge TP2 via Q + graph reduction -> out
    k_tp2<<<(E + 255) / 256, 256>>>(pos, zarr, batch, esrc, edst, out, E, P2);
}

// round 6
// speedup vs baseline: 6.6548x; 2.1330x over previous
#include <cuda_runtime.h>
#include <cuda_bf16.h>
#include <math.h>
#include <string.h>

// ============================================================================
// Problem constants
// ============================================================================
#define NN    20000
#define NGR   5000
#define GR    52             // padded per-(node,zs) G row (51 used + 1 pad)
#define QR    72             // padded per-(node,zd) Q row
#define CSTR  904            // coeffs per (zn,zd) combo (slot-major)

// ============================================================================
// Device scratch (static — no allocation allowed)
// ============================================================================
__device__ float4 g_G4[(size_t)NN * 4 * GR / 4];     // 16.6 MB G accumulators
__device__ float4 g_NS4[(size_t)NN * 12 / 4];        // padded node_sh (9 used)
__device__ float4 g_Q4[(size_t)NN * 4 * QR / 4];     // 23 MB Q tables
__device__ __align__(16) float g_C[16 * CSTR];       // fused W1*W2 operator
__device__ float4 g_out8[(size_t)NGR * 2];           // padded output accumulator

// ============================================================================
// Parameter structs
// ============================================================================
struct TP1P {
    float c000;
    float d011[3], d022[5], d101[3], d110[3], d202[5], d220[5];
    float c111[27], c112[45], c121[45], c122[75];
    float c211[45], c212[75], c221[75], c222[125];
};
struct TP2P  { float d110[3]; float d220[5]; };
struct PREPP { float s1[5]; float s20, s21, q0s; };

// ============================================================================
// Helpers
// ============================================================================
__device__ __forceinline__ void compute_sh(float x, float y, float z, float sh[9]) {
    const float s3  = 1.7320508075688772f;
    const float s15 = 3.8729833462074170f;
    const float s5  = 2.2360679774997896f;
    float r2 = x * x + y * y + z * z;
    sh[0] = 1.0f;
    sh[1] = s3 * y; sh[2] = s3 * z; sh[3] = s3 * x;
    sh[4] = s15 * x * y;
    sh[5] = s15 * y * z;
    sh[6] = 0.5f * s5 * (3.0f * z * z - r2);
    sh[7] = s15 * x * z;
    sh[8] = 0.5f * s15 * (x * x - y * y);
}

__device__ __forceinline__ void red4(float* p, float a, float b, float c, float d) {
    asm volatile("red.global.add.v4.f32 [%0], {%1,%2,%3,%4};"
                 :: "l"(p), "f"(a), "f"(b), "f"(c), "f"(d) : "memory");
}
__device__ __forceinline__ void red2(float* p, float a, float b) {
    asm volatile("red.global.add.v2.f32 [%0], {%1,%2};"
                 :: "l"(p), "f"(a), "f"(b) : "memory");
}

// ============================================================================
// K0: zero scratch
// ============================================================================
__global__ void k_zero() {
    size_t idx    = (size_t)blockIdx.x * blockDim.x + threadIdx.x;
    size_t stride = (size_t)gridDim.x * blockDim.x;
    const float4 z4 = make_float4(0.f, 0.f, 0.f, 0.f);
    const size_t ng = (size_t)NN * 4 * GR / 4;
    for (size_t j = idx; j < ng; j += stride) g_G4[j] = z4;
    for (size_t j = idx; j < (size_t)NN * 3; j += stride) g_NS4[j] = z4;
    for (size_t j = idx; j < (size_t)NGR * 2; j += stride) g_out8[j] = z4;
}

// ============================================================================
// K_prep: fused operator  g_C[zn*4+zd][slot-major 904]
//   slot layout: [0,6)Q0 ×12 | [6,9)A1 ×8 | [9,27)B1 ×16 | [27,32)A2 ×8 | [32,62)B2 ×16
// ============================================================================
__global__ void k_prep(const float* __restrict__ w1, const float* __restrict__ w2, PREPP M) {
    int combo = blockIdx.x;           // 0..15
    int zn = combo >> 2, zd = combo & 3;
    int t2 = 4 * zn + zd;
    float* C = &g_C[combo * CSTR];
    for (int f = threadIdx.x; f < CSTR; f += blockDim.x) {
        float v = 0.f;
        if (f < 72) {                                   // Q0: [s(6)][g(4)][k(3)]
            int s = f / 12, r = f % 12, g = r / 3, ki = r % 3;
            int off = (ki == 0) ? 0 : (ki == 1 ? 2048 : 5248);
            int t1 = 4 * g + zn;
            float a = 0.f;
            for (int u = 0; u < 64; u++)
                a += __ldg(w1 + off + t1 * 64 + u) * __ldg(w2 + u * 96 + t2 * 6 + s);
            v = M.q0s * M.s1[0] * a;
        } else if (f < 96) {                            // A1: [s(3)][g(4)][p(2)]
            int r = f - 72, q = r % 8, g = q / 2, p = q % 2;
            int off = p ? 6272 : 3072;
            int t1 = 4 * g + zn;
            float a = 0.f;
            for (int u = 0; u < 24; u++)
                a += __ldg(w1 + off + t1 * 24 + u) * __ldg(w2 + 6144 + u * 16 + t2);
            v = M.s20 * M.s1[1] * a;
        } else if (f < 384) {                           // B1: [slotr(18)][g(4)][p(4)]
            int r = f - 96, slotr = r / 16, q = r % 16, g = q / 4, p = q % 4;
            int w = slotr % 6;
            const int offs[4] = {1024, 1664, 3712, 4608};
            int t1 = 4 * g + zn;
            float a = 0.f;
            for (int u = 0; u < 24; u++)
                a += __ldg(w1 + offs[p] + t1 * 24 + u) * __ldg(w2 + 6528 + u * 96 + t2 * 6 + w);
            v = M.s21 * M.s1[2] * a;
        } else if (f < 424) {                           // A2: [s(5)][g(4)][p(2)]
            int r = f - 384, q = r % 8, g = q / 2, p = q % 2;
            int off = p ? 4992 : 4096;
            int t1 = 4 * g + zn;
            float a = 0.f;
            for (int u = 0; u < 16; u++)
                a += __ldg(w1 + off + t1 * 16 + u) * __ldg(w2 + 10368 + u * 16 + t2);
            v = M.s20 * M.s1[4] * a;
        } else {                                        // B2: [slotr(30)][g(4)][p(4)]
            int r = f - 424, slotr = r / 16, q = r % 16, g = q / 4, p = q % 4;
            int w = slotr % 6;
            const int offs[4] = {1408, 3456, 4352, 6656};
            int t1 = 4 * g + zn;
            float a = 0.f;
            for (int u = 0; u < 16; u++)
                a += __ldg(w1 + offs[p] + t1 * 16 + u) * __ldg(w2 + 8832 + u * 96 + t2 * 6 + w);
            v = M.s21 * M.s1[3] * a;
        }
        C[f] = v;
    }
}

// ============================================================================
// K1: per-edge SH -> vector reds into padded node_sh[dst]
// ============================================================================
__global__ void k_sh(const float* __restrict__ pos,
                     const int* __restrict__ esrc, const int* __restrict__ edst, int E) {
    int e = blockIdx.x * blockDim.x + threadIdx.x;
    if (e >= E) return;
    int s = __ldg(esrc + e), d = __ldg(edst + e);
    float x = __ldg(pos + 3 * s + 0) - __ldg(pos + 3 * d + 0);
    float y = __ldg(pos + 3 * s + 1) - __ldg(pos + 3 * d + 1);
    float z = __ldg(pos + 3 * s + 2) - __ldg(pos + 3 * d + 2);
    float sh[9];
    compute_sh(x, y, z, sh);
    float* np = reinterpret_cast<float*>(g_NS4) + (size_t)d * 12;
    red4(np + 0, sh[0], sh[1], sh[2], sh[3]);
    red4(np + 4, sh[4], sh[5], sh[6], sh[7]);
    atomicAdd(np + 8, sh[8]);
}

// ============================================================================
// K2: per-edge TP1 geometry -> vector reds into G[dst][z_src] (stride 52)
// ============================================================================
__global__ void k_tp1(const float* __restrict__ pos, const int* __restrict__ zarr,
                      const int* __restrict__ esrc, const int* __restrict__ edst,
                      int E, TP1P P) {
    int e = blockIdx.x * blockDim.x + threadIdx.x;
    if (e >= E) return;
    int s = __ldg(esrc + e), d = __ldg(edst + e);
    float x = __ldg(pos + 3 * s + 0) - __ldg(pos + 3 * d + 0);
    float y = __ldg(pos + 3 * s + 1) - __ldg(pos + 3 * d + 1);
    float z = __ldg(pos + 3 * s + 2) - __ldg(pos + 3 * d + 2);
    float sh[9];
    compute_sh(x, y, z, sh);
    const float* ns = reinterpret_cast<const float*>(g_NS4) + (size_t)s * 12;
    float4 xa03 = *reinterpret_cast<const float4*>(ns);
    float4 xa47 = *reinterpret_cast<const float4*>(ns + 4);
    float xa[9] = {xa03.x, xa03.y, xa03.z, xa03.w, xa47.x, xa47.y, xa47.z, xa47.w, ns[8]};
    int zs = __ldg(zarr + s);

    float g[51];
#pragma unroll
    for (int m = 0; m < 51; m++) g[m] = 0.f;

    float xa0 = xa[0];
    g[0] = xa0 * P.c000;
#pragma unroll
    for (int k = 0; k < 3; k++) g[1 + k] = xa0 * sh[1 + k] * P.d011[k];       // p1 (diag)
#pragma unroll
    for (int k = 0; k < 5; k++) g[4 + k] = xa0 * sh[4 + k] * P.d022[k];       // p2 (diag)
#pragma unroll
    for (int k = 0; k < 3; k++) g[9 + k] = xa[1 + k] * P.d101[k];             // p3 (diag)
    {                                                                          // p4 (diag dot)
        float a = 0.f;
#pragma unroll
        for (int i = 0; i < 3; i++) a += xa[1 + i] * sh[1 + i] * P.d110[i];
        g[12] = a;
    }
#pragma unroll
    for (int i = 0; i < 3; i++) {                      // p5->13 (c111), p6->16 (c112)
#pragma unroll
        for (int j = 0; j < 3; j++) {
            float f = xa[1 + i] * sh[1 + j];
#pragma unroll
            for (int k = 0; k < 3; k++) g[13 + k] += f * P.c111[(i * 3 + j) * 3 + k];
#pragma unroll
            for (int k = 0; k < 5; k++) g[16 + k] += f * P.c112[(i * 3 + j) * 5 + k];
        }
    }
#pragma unroll
    for (int i = 0; i < 3; i++) {                      // p7->21 (c121), p8->24 (c122)
#pragma unroll
        for (int j = 0; j < 5; j++) {
            float f = xa[1 + i] * sh[4 + j];
#pragma unroll
            for (int k = 0; k < 3; k++) g[21 + k] += f * P.c121[(i * 5 + j) * 3 + k];
#pragma unroll
            for (int k = 0; k < 5; k++) g[24 + k] += f * P.c122[(i * 5 + j) * 5 + k];
        }
    }
#pragma unroll
    for (int k = 0; k < 5; k++) g[29 + k] = xa[4 + k] * P.d202[k];            // p9 (diag)
#pragma unroll
    for (int i = 0; i < 5; i++) {                      // p10->34 (c211), p11->37 (c212)
#pragma unroll
        for (int j = 0; j < 3; j++) {
            float f = xa[4 + i] * sh[1 + j];
#pragma unroll
            for (int k = 0; k < 3; k++) g[34 + k] += f * P.c211[(i * 3 + j) * 3 + k];
#pragma unroll
            for (int k = 0; k < 5; k++) g[37 + k] += f * P.c212[(i * 3 + j) * 5 + k];
        }
    }
    {                                                                          // p12 (diag dot)
        float a = 0.f;
#pragma unroll
        for (int i = 0; i < 5; i++) a += xa[4 + i] * sh[4 + i] * P.d220[i];
        g[42] = a;
    }
#pragma unroll
    for (int i = 0; i < 5; i++) {                      // p13->43 (c221), p14->46 (c222)
#pragma unroll
        for (int j = 0; j < 5; j++) {
            float f = xa[4 + i] * sh[4 + j];
#pragma unroll
            for (int k = 0; k < 3; k++) g[43 + k] += f * P.c221[(i * 5 + j) * 3 + k];
#pragma unroll
            for (int k = 0; k < 5; k++) g[46 + k] += f * P.c222[(i * 5 + j) * 5 + k];
        }
    }

    float* Gp = reinterpret_cast<float*>(g_G4) + ((size_t)d * 4 + zs) * GR;
#pragma unroll
    for (int m = 0; m < 48; m += 4) red4(Gp + m, g[m], g[m + 1], g[m + 2], g[m + 3]);
    red2(Gp + 48, g[48], g[49]);
    atomicAdd(Gp + 50, g[50]);
}

// ============================================================================
// K3: Q[n][zd][·] = fused sparse operator applied to G[n].
//     Block = 256 thr = 2 nodes x 4 warps; warp = (node, zd); lane -> 2 slots.
// ============================================================================
__global__ void k_q(const int* __restrict__ zarr) {
    __shared__ float sG[2][4 * GR];
    int tid = threadIdx.x;
    int warp = tid >> 5, lane = tid & 31;
    int local = warp >> 2, zd = warp & 3;
    int n = blockIdx.x * 2 + local;

    // load 2 G rows (2 x 208 floats) coalesced as float4
    {
        const float4* src = &g_G4[(size_t)blockIdx.x * 2 * (4 * GR / 4)];
        float4* dst = reinterpret_cast<float4*>(&sG[0][0]);
        for (int i = tid; i < 2 * (4 * GR / 4); i += 256) dst[i] = src[i];
    }
    __syncthreads();

    int zn = __ldg(zarr + n);
    int combo = zn * 4 + zd;
    const float4* C4 = reinterpret_cast<const float4*>(g_C) + combo * (CSTR / 4);
    const float* Gn = &sG[local][0];
    float* Qrow = reinterpret_cast<float*>(g_Q4) + ((size_t)n * 4 + zd) * QR;

    if (lane == 31) {
        // zero the 10 pad positions
        Qrow[6] = 0.f; Qrow[7] = 0.f;
        Qrow[15] = 0.f; Qrow[23] = 0.f; Qrow[31] = 0.f;
        Qrow[39] = 0.f; Qrow[47] = 0.f; Qrow[55] = 0.f;
        Qrow[63] = 0.f; Qrow[71] = 0.f;
        return;
    }

    const int K0[3]  = {0, 12, 42};
    const int KA1[2] = {13, 43};
    const int KB1[4] = {1, 9, 21, 34};
    const int KA2[2] = {24, 37};
    const int KB2[4] = {4, 16, 29, 46};

#pragma unroll
    for (int half = 0; half < 2; half++) {
        int s = lane + half * 31;       // 0..30, 31..61
        float acc = 0.f;
        int pos;
        if (s < 6) {                     // Q0: 12 coeffs [g][k3]
            float4 a = C4[s * 3], b = C4[s * 3 + 1], c = C4[s * 3 + 2];
            float cc[12] = {a.x, a.y, a.z, a.w, b.x, b.y, b.z, b.w, c.x, c.y, c.z, c.w};
#pragma unroll
            for (int g = 0; g < 4; g++)
#pragma unroll
                for (int k = 0; k < 3; k++)
                    acc += cc[g * 3 + k] * Gn[g * GR + K0[k]];
            pos = s;
        } else if (s < 9) {              // A1: 8 coeffs [g][p2]
            int i = s - 6;
            float4 a = C4[18 + i * 2], b = C4[18 + i * 2 + 1];
            float cc[8] = {a.x, a.y, a.z, a.w, b.x, b.y, b.z, b.w};
#pragma unroll
            for (int g = 0; g < 4; g++)
#pragma unroll
                for (int p = 0; p < 2; p++)
                    acc += cc[g * 2 + p] * Gn[g * GR + KA1[p] + i];
            pos = 8 + i * 8;
        } else if (s < 27) {             // B1: 16 coeffs [g][p4]
            int r = s - 9, i = r / 6, w = r - i * 6;
            float4 a = C4[24 + r * 4], b = C4[24 + r * 4 + 1],
                   c = C4[24 + r * 4 + 2], dd = C4[24 + r * 4 + 3];
            float cc[16] = {a.x, a.y, a.z, a.w, b.x, b.y, b.z, b.w,
                            c.x, c.y, c.z, c.w, dd.x, dd.y, dd.z, dd.w};
#pragma unroll
            for (int g = 0; g < 4; g++)
#pragma unroll
                for (int p = 0; p < 4; p++)
                    acc += cc[g * 4 + p] * Gn[g * GR + KB1[p] + i];
            pos = 9 + i * 8 + w;
        } else if (s < 32) {             // A2: 8 coeffs [g][p2]
            int i = s - 27;
            float4 a = C4[96 + i * 2], b = C4[96 + i * 2 + 1];
            float cc[8] = {a.x, a.y, a.z, a.w, b.x, b.y, b.z, b.w};
#pragma unroll
            for (int g = 0; g < 4; g++)
#pragma unroll
                for (int p = 0; p < 2; p++)
                    acc += cc[g * 2 + p] * Gn[g * GR + KA2[p] + i];
            pos = 32 + i * 8;
        } else {                         // B2: 16 coeffs [g][p4]
            int r = s - 32, i = r / 6, w = r - i * 6;
            float4 a = C4[106 + r * 4], b = C4[106 + r * 4 + 1],
                   c = C4[106 + r * 4 + 2], dd = C4[106 + r * 4 + 3];
            float cc[16] = {a.x, a.y, a.z, a.w, b.x, b.y, b.z, b.w,
                            c.x, c.y, c.z, c.w, dd.x, dd.y, dd.z, dd.w};
#pragma unroll
            for (int g = 0; g < 4; g++)
#pragma unroll
                for (int p = 0; p < 4; p++)
                    acc += cc[g * 4 + p] * Gn[g * GR + KB2[p] + i];
            pos = 33 + i * 8 + w;
        }
        Qrow[pos] = acc;
    }
}

// ============================================================================
// K4: per-edge TP2 via Q (vectorized) -> padded graph accumulator (2 v4 reds)
// ============================================================================
__global__ void k_tp2(const float* __restrict__ pos, const int* __restrict__ zarr,
                      const int* __restrict__ batch,
                      const int* __restrict__ esrc, const int* __restrict__ edst,
                      int E, TP2P P) {
    int e = blockIdx.x * blockDim.x + threadIdx.x;
    if (e >= E) return;
    int s = __ldg(esrc + e), d = __ldg(edst + e);
    float x = __ldg(pos + 3 * s + 0) - __ldg(pos + 3 * d + 0);
    float y = __ldg(pos + 3 * s + 1) - __ldg(pos + 3 * d + 1);
    float z = __ldg(pos + 3 * s + 2) - __ldg(pos + 3 * d + 2);
    float sh[9];
    compute_sh(x, y, z, sh);
    float v1[3], v2[5];
#pragma unroll
    for (int i = 0; i < 3; i++) v1[i] = sh[1 + i] * P.d110[i];
#pragma unroll
    for (int i = 0; i < 5; i++) v2[i] = sh[4 + i] * P.d220[i];

    int zd = __ldg(zarr + d);
    const float4* q4 = &g_Q4[((size_t)s * 4 + zd) * (QR / 4)];

    float4 qa = __ldg(q4);          // Q0 w0..3
    float4 qb = __ldg(q4 + 1);      // Q0 w4,w5, pad, pad
    float acc0 = 0.f;
    float a0 = qa.x, a1 = qa.y, a2 = qa.z, a3 = qa.w, a4 = qb.x, a5 = qb.y;

#pragma unroll
    for (int i = 0; i < 3; i++) {
        float v = v1[i];
        float4 b0 = __ldg(q4 + 2 + i * 2);      // A1_i, B w0..2
        float4 b1 = __ldg(q4 + 3 + i * 2);      // B w3..5, pad
        acc0 += v * b0.x;
        a0 += v * b0.y; a1 += v * b0.z; a2 += v * b0.w;
        a3 += v * b1.x; a4 += v * b1.y; a5 += v * b1.z;
    }
#pragma unroll
    for (int i = 0; i < 5; i++) {
        float v = v2[i];
        float4 b0 = __ldg(q4 + 8 + i * 2);      // A2_i, B w0..2
        float4 b1 = __ldg(q4 + 9 + i * 2);      // B w3..5, pad
        acc0 += v * b0.x;
        a0 += v * b0.y; a1 += v * b0.z; a2 += v * b0.w;
        a3 += v * b1.x; a4 += v * b1.y; a5 += v * b1.z;
    }

    int g = __ldg(batch + d);
    float* og = reinterpret_cast<float*>(g_out8) + (size_t)g * 8;
    red4(og + 0, acc0, a0, a1, a2);
    red4(og + 4, a3, a4, a5, 0.f);
}

// ============================================================================
// K5: copy padded accumulator -> out (5000 x 7)
// ============================================================================
__global__ void k_final(float* __restrict__ out) {
    int i = blockIdx.x * blockDim.x + threadIdx.x;
    if (i >= NGR * 7) return;
    int g = i / 7, j = i - g * 7;
    out[i] = reinterpret_cast<const float*>(g_out8)[g * 8 + j];
}

// ============================================================================
// Host: Wigner 3j (mirrors reference)
// ============================================================================
static double hfact(int n) { double r = 1.0; for (int i = 2; i <= n; i++) r *= (double)i; return r; }

static double hcg(int j1, int j2, int j3, int m1, int m2, int m3) {
    if (m1 + m2 != m3) return 0.0;
    double pre = sqrt((2.0 * j3 + 1.0) * hfact(j3 + j1 - j2) * hfact(j3 - j1 + j2) *
                      hfact(j1 + j2 - j3) / hfact(j1 + j2 + j3 + 1));
    pre *= sqrt(hfact(j3 + m3) * hfact(j3 - m3) * hfact(j1 - m1) * hfact(j1 + m1) *
                hfact(j2 - m2) * hfact(j2 + m2));
    int kmin = 0;
    if (j2 - j3 - m1 > kmin) kmin = j2 - j3 - m1;
    if (j1 - j3 + m2 > kmin) kmin = j1 - j3 + m2;
    int kmax = j1 + j2 - j3;
    if (j1 - m1 < kmax) kmax = j1 - m1;
    if (j2 + m2 < kmax) kmax = j2 + m2;
    double s = 0.0;
    for (int k = kmin; k <= kmax; k++) {
        double den = hfact(k) * hfact(j1 + j2 - j3 - k) * hfact(j1 - m1 - k) *
                     hfact(j2 + m2 - k) * hfact(j3 - j2 + m1 + k) * hfact(j3 - j1 - m2 + k);
        s += ((k & 1) ? -1.0 : 1.0) / den;
    }
    return pre * s;
}

static void humat(int l, double Ur[5][5], double Ui[5][5]) {
    for (int a = 0; a < 5; a++) for (int b = 0; b < 5; b++) { Ur[a][b] = 0.0; Ui[a][b] = 0.0; }
    double is2 = 1.0 / sqrt(2.0);
    for (int m = -l; m <= l; m++) {
        int r = m + l;
        if (m > 0) {
            Ur[r][l - m] = is2;
            Ur[r][l + m] = ((m & 1) ? -1.0 : 1.0) * is2;
        } else if (m == 0) {
            Ur[l][l] = 1.0;
        } else {
            Ui[r][l + m] = is2;
            Ui[r][l - m] = -(((-m) & 1) ? -1.0 : 1.0) * is2;
        }
    }
}

static void hw3j(int l1, int l2, int l3, float* out) {
    int n1 = 2 * l1 + 1, n2 = 2 * l2 + 1, n3 = 2 * l3 + 1;
    double C[5][5][5];
    memset(C, 0, sizeof(C));
    for (int m1 = -l1; m1 <= l1; m1++)
        for (int m2 = -l2; m2 <= l2; m2++) {
            int m3 = m1 + m2;
            if (m3 < -l3 || m3 > l3) continue;
            C[m1 + l1][m2 + l2][m3 + l3] = hcg(l1, l2, l3, m1, m2, m3);
        }
    double U1r[5][5], U1i[5][5], U2r[5][5], U2i[5][5], U3r[5][5], U3i[5][5];
    humat(l1, U1r, U1i); humat(l2, U2r, U2i); humat(l3, U3r, U3i);
    double Tre[5][5][5], Tim[5][5][5];
    double maxr = 0.0, maxi = 0.0;
    for (int a = 0; a < n1; a++)
        for (int b = 0; b < n2; b++)
            for (int c = 0; c < n3; c++) {
                double sr = 0.0, si = 0.0;
                for (int m = 0; m < n1; m++)
                    for (int n = 0; n < n2; n++)
                        for (int o = 0; o < n3; o++) {
                            double cv = C[m][n][o];
                            if (cv == 0.0) continue;
                            double ar = U1r[a][m], ai = U1i[a][m];
                            double br = U2r[b][n], bi = U2i[b][n];
                            double qr = ar * br - ai * bi, qi = ar * bi + ai * br;
                            double cr = U3r[c][o], ci = -U3i[c][o];
                            double rr = qr * cr - qi * ci, ri = qr * ci + qi * cr;
                            sr += rr * cv; si += ri * cv;
                        }
                Tre[a][b][c] = sr; Tim[a][b][c] = si;
                if (fabs(sr) > maxr) maxr = fabs(sr);
                if (fabs(si) > maxi) maxi = fabs(si);
            }
    bool useR = (maxr >= maxi);
    double nrm = 0.0;
    for (int a = 0; a < n1; a++)
        for (int b = 0; b < n2; b++)
            for (int c = 0; c < n3; c++) {
                double v = useR ? Tre[a][b][c] : Tim[a][b][c];
                nrm += v * v;
            }
    nrm = sqrt(nrm);
    for (int a = 0; a < n1; a++)
        for (int b = 0; b < n2; b++)
            for (int c = 0; c < n3; c++) {
                double v = useR ? Tre[a][b][c] : Tim[a][b][c];
                out[(a * n2 + b) * n3 + c] = (float)(v / nrm);
            }
}

// ============================================================================
// kernel_launch
// ============================================================================
extern "C" void kernel_launch(void* const* d_in, const int* in_sizes, int n_in,
                              void* d_out, int out_size) {
    const float* pos   = (const float*)d_in[0];
    const int*   zarr  = (const int*)  d_in[1];
    const int*   batch = (const int*)  d_in[2];
    const int*   esrc  = (const int*)  d_in[3];
    const int*   edst  = (const int*)  d_in[4];
    const float* w1    = (const float*)d_in[5];
    const float* w2    = (const float*)d_in[6];
    float*       out   = (float*)d_out;
    int E = in_sizes[3];

    // ---- host precompute (capture-time only) ----
    float c000, c011[9], c022[25], c101[9], c110[9], c202[25], c220[25];
    TP1P P;
    hw3j(0, 0, 0, &c000);
    hw3j(0, 1, 1, c011);  hw3j(0, 2, 2, c022);
    hw3j(1, 0, 1, c101);  hw3j(1, 1, 0, c110);
    hw3j(2, 0, 2, c202);  hw3j(2, 2, 0, c220);
    hw3j(1, 1, 1, P.c111); hw3j(1, 1, 2, P.c112);
    hw3j(1, 2, 1, P.c121); hw3j(1, 2, 2, P.c122);
    hw3j(2, 1, 1, P.c211); hw3j(2, 1, 2, P.c212);
    hw3j(2, 2, 1, P.c221); hw3j(2, 2, 2, P.c222);
    P.c000 = c000;
    for (int k = 0; k < 3; k++) { P.d011[k] = c011[k * 3 + k]; P.d101[k] = c101[k * 3 + k]; P.d110[k] = c110[k * 3 + k]; }
    for (int k = 0; k < 5; k++) { P.d022[k] = c022[k * 5 + k]; P.d202[k] = c202[k * 5 + k]; P.d220[k] = c220[k * 5 + k]; }

    PREPP M;
    {
        const double fan1[5] = {48.0, 32.0, 64.0, 64.0, 32.0};
        const int l3c[5] = {0, 1, 1, 2, 2};
        for (int c = 0; c < 5; c++)
            M.s1[c] = (float)(4.0 * sqrt(2.0 * l3c[c] + 1.0) / sqrt(fan1[c]) / 3.0);
        M.s20 = (float)(2.0 / (sqrt(3.0) * sqrt(640.0)));
        M.s21 = (float)(2.0 / (sqrt(3.0) * sqrt(1664.0)));
        M.q0s = c000 * M.s21;
    }

    TP2P P2;
    memcpy(P2.d110, P.d110, sizeof(P2.d110));
    memcpy(P2.d220, P.d220, sizeof(P2.d220));

    // ---- pipeline ----
    k_zero<<<2048, 256>>>();
    k_prep<<<16, 256>>>(w1, w2, M);
    k_sh<<<(E + 255) / 256, 256>>>(pos, esrc, edst, E);
    k_tp1<<<(E + 255) / 256, 256>>>(pos, zarr, esrc, edst, E, P);
    k_q<<<NN / 2, 256>>>(zarr);
    k_tp2<<<(E + 255) / 256, 256>>>(pos, zarr, batch, esrc, edst, E, P2);
    k_final<<<(NGR * 7 + 255) / 256, 256>>>(out);
}

// round 7
// speedup vs baseline: 7.6382x; 1.1478x over previous
#include <cuda_runtime.h>
#include <cuda_bf16.h>
#include <math.h>
#include <string.h>

// ============================================================================
// Problem constants
// ============================================================================
#define NN    20000
#define NGR   5000
#define EMAX  320000
#define GR    52             // padded per-(node,zs) G row (51 used + 1 pad)
#define QR    72             // padded per-(node,zd) Q row
#define CSTR  904            // coeffs per (zn,zd) combo (slot-major)

// ============================================================================
// Device scratch (static — no allocation allowed).
// INVARIANT: g_G4, g_NS4, g_out8 are zero at kernel_launch entry (zero-init at
// load; each consumer kernel re-zeroes what it read, restoring the invariant
// for the next graph replay).
// ============================================================================
__device__ float4 g_G4[(size_t)NN * 4 * GR / 4];     // 16.6 MB G accumulators
__device__ float4 g_NS4[(size_t)NN * 12 / 4];        // padded node_sh (9 used)
__device__ float4 g_Q4[(size_t)NN * 4 * QR / 4];     // 23 MB Q tables
__device__ __align__(16) float g_C[16 * CSTR];       // fused W1*W2 operator
__device__ float4 g_out8[(size_t)NGR * 2];           // padded output accumulator
__device__ float4 g_ER[EMAX];                        // per-edge record: ev + meta

// ============================================================================
// Parameter structs
// ============================================================================
struct TP1P {
    float c000;
    float d011[3], d022[5], d101[3], d110[3], d202[5], d220[5];
    float c111[27], c112[45], c121[45], c122[75];
    float c211[45], c212[75], c221[75], c222[125];
};
struct TP2P  { float d110[3]; float d220[5]; };
struct PREPP { float s1[5]; float s20, s21, q0s; };

// ============================================================================
// Helpers
// ============================================================================
__device__ __forceinline__ void compute_sh(float x, float y, float z, float sh[9]) {
    const float s3  = 1.7320508075688772f;
    const float s15 = 3.8729833462074170f;
    const float s5  = 2.2360679774997896f;
    float r2 = x * x + y * y + z * z;
    sh[0] = 1.0f;
    sh[1] = s3 * y; sh[2] = s3 * z; sh[3] = s3 * x;
    sh[4] = s15 * x * y;
    sh[5] = s15 * y * z;
    sh[6] = 0.5f * s5 * (3.0f * z * z - r2);
    sh[7] = s15 * x * z;
    sh[8] = 0.5f * s15 * (x * x - y * y);
}

__device__ __forceinline__ void red4(float* p, float a, float b, float c, float d) {
    asm volatile("red.global.add.v4.f32 [%0], {%1,%2,%3,%4};"
                 :: "l"(p), "f"(a), "f"(b), "f"(c), "f"(d) : "memory");
}

// ============================================================================
// K1 (fused): edge pass 1 (SH reds + edge record) + operator prep stripes.
//   blocks [0, EB): edges.  blocks [EB, EB+64): 16 combos x 4 slices of g_C.
// ============================================================================
__global__ void k_shp(const float* __restrict__ pos, const int* __restrict__ zarr,
                      const int* __restrict__ batch,
                      const int* __restrict__ esrc, const int* __restrict__ edst,
                      const float* __restrict__ w1, const float* __restrict__ w2,
                      int E, int EB, PREPP M) {
    int b = blockIdx.x;
    if (b < EB) {
        int e = b * 256 + threadIdx.x;
        if (e >= E) return;
        int s = __ldg(esrc + e), d = __ldg(edst + e);
        float x = __ldg(pos + 3 * s + 0) - __ldg(pos + 3 * d + 0);
        float y = __ldg(pos + 3 * s + 1) - __ldg(pos + 3 * d + 1);
        float z = __ldg(pos + 3 * s + 2) - __ldg(pos + 3 * d + 2);
        float sh[9];
        compute_sh(x, y, z, sh);
        float* np = reinterpret_cast<float*>(g_NS4) + (size_t)d * 12;
        red4(np + 0, sh[0], sh[1], sh[2], sh[3]);
        red4(np + 4, sh[4], sh[5], sh[6], sh[7]);
        red4(np + 8, sh[8], 0.f, 0.f, 0.f);
        int bits = __ldg(zarr + s) | (__ldg(zarr + d) << 2) | (__ldg(batch + d) << 4);
        g_ER[e] = make_float4(x, y, z, __int_as_float(bits));
        return;
    }
    // ---- operator prep ----
    int r = b - EB;                    // 0..63
    int combo = r >> 2, slice = r & 3;
    int zn = combo >> 2, zd = combo & 3;
    int t2 = 4 * zn + zd;
    int f = slice * 256 + threadIdx.x;
    if (f >= CSTR) return;
    float v = 0.f;
    if (f < 72) {                                   // Q0: [s(6)][g(4)][k(3)]
        int s = f / 12, rr = f % 12, g = rr / 3, ki = rr % 3;
        int off = (ki == 0) ? 0 : (ki == 1 ? 2048 : 5248);
        int t1 = 4 * g + zn;
        float a = 0.f;
        for (int u = 0; u < 64; u++)
            a += __ldg(w1 + off + t1 * 64 + u) * __ldg(w2 + u * 96 + t2 * 6 + s);
        v = M.q0s * M.s1[0] * a;
    } else if (f < 96) {                            // A1: [s(3)][g(4)][p(2)]
        int rr = f - 72, q = rr % 8, g = q / 2, p = q % 2;
        int off = p ? 6272 : 3072;
        int t1 = 4 * g + zn;
        float a = 0.f;
        for (int u = 0; u < 24; u++)
            a += __ldg(w1 + off + t1 * 24 + u) * __ldg(w2 + 6144 + u * 16 + t2);
        v = M.s20 * M.s1[1] * a;
    } else if (f < 384) {                           // B1: [slotr(18)][g(4)][p(4)]
        int rr = f - 96, slotr = rr / 16, q = rr % 16, g = q / 4, p = q % 4;
        int w = slotr % 6;
        const int offs[4] = {1024, 1664, 3712, 4608};
        int t1 = 4 * g + zn;
        float a = 0.f;
        for (int u = 0; u < 24; u++)
            a += __ldg(w1 + offs[p] + t1 * 24 + u) * __ldg(w2 + 6528 + u * 96 + t2 * 6 + w);
        v = M.s21 * M.s1[2] * a;
    } else if (f < 424) {                           // A2: [s(5)][g(4)][p(2)]
        int rr = f - 384, q = rr % 8, g = q / 2, p = q % 2;
        int off = p ? 4992 : 4096;
        int t1 = 4 * g + zn;
        float a = 0.f;
        for (int u = 0; u < 16; u++)
            a += __ldg(w1 + off + t1 * 16 + u) * __ldg(w2 + 10368 + u * 16 + t2);
        v = M.s20 * M.s1[4] * a;
    } else {                                        // B2: [slotr(30)][g(4)][p(4)]
        int rr = f - 424, slotr = rr / 16, q = rr % 16, g = q / 4, p = q % 4;
        int w = slotr % 6;
        const int offs[4] = {1408, 3456, 4352, 6656};
        int t1 = 4 * g + zn;
        float a = 0.f;
        for (int u = 0; u < 16; u++)
            a += __ldg(w1 + offs[p] + t1 * 16 + u) * __ldg(w2 + 8832 + u * 96 + t2 * 6 + w);
        v = M.s21 * M.s1[3] * a;
    }
    g_C[combo * CSTR + f] = v;
}

// ============================================================================
// K2: per-edge TP1 geometry -> 13 vector reds into G[dst][z_src] (stride 52)
// ============================================================================
__global__ void k_tp1(const int* __restrict__ esrc, const int* __restrict__ edst,
                      int E, TP1P P) {
    int e = blockIdx.x * blockDim.x + threadIdx.x;
    if (e >= E) return;
    float4 er = g_ER[e];
    int s = __ldg(esrc + e), d = __ldg(edst + e);
    int zs = __float_as_int(er.w) & 3;
    float sh[9];
    compute_sh(er.x, er.y, er.z, sh);
    const float* ns = reinterpret_cast<const float*>(g_NS4) + (size_t)s * 12;
    float4 xa03 = *reinterpret_cast<const float4*>(ns);
    float4 xa47 = *reinterpret_cast<const float4*>(ns + 4);
    float xa[9] = {xa03.x, xa03.y, xa03.z, xa03.w, xa47.x, xa47.y, xa47.z, xa47.w, ns[8]};

    float g[51];
#pragma unroll
    for (int m = 0; m < 51; m++) g[m] = 0.f;

    float xa0 = xa[0];
    g[0] = xa0 * P.c000;
#pragma unroll
    for (int k = 0; k < 3; k++) g[1 + k] = xa0 * sh[1 + k] * P.d011[k];       // p1 (diag)
#pragma unroll
    for (int k = 0; k < 5; k++) g[4 + k] = xa0 * sh[4 + k] * P.d022[k];       // p2 (diag)
#pragma unroll
    for (int k = 0; k < 3; k++) g[9 + k] = xa[1 + k] * P.d101[k];             // p3 (diag)
    {                                                                          // p4 (diag dot)
        float a = 0.f;
#pragma unroll
        for (int i = 0; i < 3; i++) a += xa[1 + i] * sh[1 + i] * P.d110[i];
        g[12] = a;
    }
#pragma unroll
    for (int i = 0; i < 3; i++) {                      // p5->13 (c111), p6->16 (c112)
#pragma unroll
        for (int j = 0; j < 3; j++) {
            float f = xa[1 + i] * sh[1 + j];
#pragma unroll
            for (int k = 0; k < 3; k++) g[13 + k] += f * P.c111[(i * 3 + j) * 3 + k];
#pragma unroll
            for (int k = 0; k < 5; k++) g[16 + k] += f * P.c112[(i * 3 + j) * 5 + k];
        }
    }
#pragma unroll
    for (int i = 0; i < 3; i++) {                      // p7->21 (c121), p8->24 (c122)
#pragma unroll
        for (int j = 0; j < 5; j++) {
            float f = xa[1 + i] * sh[4 + j];
#pragma unroll
            for (int k = 0; k < 3; k++) g[21 + k] += f * P.c121[(i * 5 + j) * 3 + k];
#pragma unroll
            for (int k = 0; k < 5; k++) g[24 + k] += f * P.c122[(i * 5 + j) * 5 + k];
        }
    }
#pragma unroll
    for (int k = 0; k < 5; k++) g[29 + k] = xa[4 + k] * P.d202[k];            // p9 (diag)
#pragma unroll
    for (int i = 0; i < 5; i++) {                      // p10->34 (c211), p11->37 (c212)
#pragma unroll
        for (int j = 0; j < 3; j++) {
            float f = xa[4 + i] * sh[1 + j];
#pragma unroll
            for (int k = 0; k < 3; k++) g[34 + k] += f * P.c211[(i * 3 + j) * 3 + k];
#pragma unroll
            for (int k = 0; k < 5; k++) g[37 + k] += f * P.c212[(i * 3 + j) * 5 + k];
        }
    }
    {                                                                          // p12 (diag dot)
        float a = 0.f;
#pragma unroll
        for (int i = 0; i < 5; i++) a += xa[4 + i] * sh[4 + i] * P.d220[i];
        g[42] = a;
    }
#pragma unroll
    for (int i = 0; i < 5; i++) {                      // p13->43 (c221), p14->46 (c222)
#pragma unroll
        for (int j = 0; j < 5; j++) {
            float f = xa[4 + i] * sh[4 + j];
#pragma unroll
            for (int k = 0; k < 3; k++) g[43 + k] += f * P.c221[(i * 5 + j) * 3 + k];
#pragma unroll
            for (int k = 0; k < 5; k++) g[46 + k] += f * P.c222[(i * 5 + j) * 5 + k];
        }
    }

    float* Gp = reinterpret_cast<float*>(g_G4) + ((size_t)d * 4 + zs) * GR;
#pragma unroll
    for (int m = 0; m < 48; m += 4) red4(Gp + m, g[m], g[m + 1], g[m + 2], g[m + 3]);
    red4(Gp + 48, g[48], g[49], g[50], 0.f);           // index 51 is a pad
}

// ============================================================================
// K3: Q[n][zd][·] = fused sparse operator applied to G[n]; then re-zero the
//     G and node_sh rows this block consumed (restores the zero invariant).
//     Block = 256 thr = 2 nodes x 4 warps; warp = (node, zd); lane -> 2 slots.
// ============================================================================
__global__ void k_q(const int* __restrict__ zarr) {
    __shared__ float sG[2][4 * GR];
    int tid = threadIdx.x;
    int warp = tid >> 5, lane = tid & 31;
    int local = warp >> 2, zd = warp & 3;
    int n = blockIdx.x * 2 + local;

    // load 2 G rows (2 x 208 floats = 104 float4) coalesced
    {
        const float4* src = &g_G4[(size_t)blockIdx.x * 104];
        float4* dst = reinterpret_cast<float4*>(&sG[0][0]);
        if (tid < 104) dst[tid] = src[tid];
    }
    __syncthreads();

    // re-zero consumed scratch for the next graph replay
    {
        const float4 z4 = make_float4(0.f, 0.f, 0.f, 0.f);
        if (tid < 104) g_G4[(size_t)blockIdx.x * 104 + tid] = z4;
        else if (tid < 110) g_NS4[(size_t)blockIdx.x * 6 + (tid - 104)] = z4;
    }

    int zn = __ldg(zarr + n);
    int combo = zn * 4 + zd;
    const float4* C4 = reinterpret_cast<const float4*>(g_C) + combo * (CSTR / 4);
    const float* Gn = &sG[local][0];
    float* Qrow = reinterpret_cast<float*>(g_Q4) + ((size_t)n * 4 + zd) * QR;

    if (lane == 31) {
        // zero the 10 pad positions
        Qrow[6] = 0.f; Qrow[7] = 0.f;
        Qrow[15] = 0.f; Qrow[23] = 0.f; Qrow[31] = 0.f;
        Qrow[39] = 0.f; Qrow[47] = 0.f; Qrow[55] = 0.f;
        Qrow[63] = 0.f; Qrow[71] = 0.f;
        return;
    }

    const int K0[3]  = {0, 12, 42};
    const int KA1[2] = {13, 43};
    const int KB1[4] = {1, 9, 21, 34};
    const int KA2[2] = {24, 37};
    const int KB2[4] = {4, 16, 29, 46};

#pragma unroll
    for (int half = 0; half < 2; half++) {
        int s = lane + half * 31;       // 0..30, 31..61
        float acc = 0.f;
        int pos;
        if (s < 6) {                     // Q0: 12 coeffs [g][k3]
            float4 a = C4[s * 3], b = C4[s * 3 + 1], c = C4[s * 3 + 2];
            float cc[12] = {a.x, a.y, a.z, a.w, b.x, b.y, b.z, b.w, c.x, c.y, c.z, c.w};
#pragma unroll
            for (int g = 0; g < 4; g++)
#pragma unroll
                for (int k = 0; k < 3; k++)
                    acc += cc[g * 3 + k] * Gn[g * GR + K0[k]];
            pos = s;
        } else if (s < 9) {              // A1: 8 coeffs [g][p2]
            int i = s - 6;
            float4 a = C4[18 + i * 2], b = C4[18 + i * 2 + 1];
            float cc[8] = {a.x, a.y, a.z, a.w, b.x, b.y, b.z, b.w};
#pragma unroll
            for (int g = 0; g < 4; g++)
#pragma unroll
                for (int p = 0; p < 2; p++)
                    acc += cc[g * 2 + p] * Gn[g * GR + KA1[p] + i];
            pos = 8 + i * 8;
        } else if (s < 27) {             // B1: 16 coeffs [g][p4]
            int r = s - 9, i = r / 6, w = r - i * 6;
            float4 a = C4[24 + r * 4], b = C4[24 + r * 4 + 1],
                   c = C4[24 + r * 4 + 2], dd = C4[24 + r * 4 + 3];
            float cc[16] = {a.x, a.y, a.z, a.w, b.x, b.y, b.z, b.w,
                            c.x, c.y, c.z, c.w, dd.x, dd.y, dd.z, dd.w};
#pragma unroll
            for (int g = 0; g < 4; g++)
#pragma unroll
                for (int p = 0; p < 4; p++)
                    acc += cc[g * 4 + p] * Gn[g * GR + KB1[p] + i];
            pos = 9 + i * 8 + w;
        } else if (s < 32) {             // A2: 8 coeffs [g][p2]
            int i = s - 27;
            float4 a = C4[96 + i * 2], b = C4[96 + i * 2 + 1];
            float cc[8] = {a.x, a.y, a.z, a.w, b.x, b.y, b.z, b.w};
#pragma unroll
            for (int g = 0; g < 4; g++)
#pragma unroll
                for (int p = 0; p < 2; p++)
                    acc += cc[g * 2 + p] * Gn[g * GR + KA2[p] + i];
            pos = 32 + i * 8;
        } else {                         // B2: 16 coeffs [g][p4]
            int r = s - 32, i = r / 6, w = r - i * 6;
            float4 a = C4[106 + r * 4], b = C4[106 + r * 4 + 1],
                   c = C4[106 + r * 4 + 2], dd = C4[106 + r * 4 + 3];
            float cc[16] = {a.x, a.y, a.z, a.w, b.x, b.y, b.z, b.w,
                            c.x, c.y, c.z, c.w, dd.x, dd.y, dd.z, dd.w};
#pragma unroll
            for (int g = 0; g < 4; g++)
#pragma unroll
                for (int p = 0; p < 4; p++)
                    acc += cc[g * 4 + p] * Gn[g * GR + KB2[p] + i];
            pos = 33 + i * 8 + w;
        }
        Qrow[pos] = acc;
    }
}

// ============================================================================
// K4: per-edge TP2 via Q (vectorized) -> padded graph accumulator (2 v4 reds)
// ============================================================================
__global__ void k_tp2(const int* __restrict__ esrc, int E, TP2P P) {
    int e = blockIdx.x * blockDim.x + threadIdx.x;
    if (e >= E) return;
    float4 er = g_ER[e];
    int s = __ldg(esrc + e);
    int bits = __float_as_int(er.w);
    int zd = (bits >> 2) & 3;
    int g = bits >> 4;
    float sh[9];
    compute_sh(er.x, er.y, er.z, sh);
    float v1[3], v2[5];
#pragma unroll
    for (int i = 0; i < 3; i++) v1[i] = sh[1 + i] * P.d110[i];
#pragma unroll
    for (int i = 0; i < 5; i++) v2[i] = sh[4 + i] * P.d220[i];

    const float4* q4 = &g_Q4[((size_t)s * 4 + zd) * (QR / 4)];

    float4 qa = __ldg(q4);          // Q0 w0..3
    float4 qb = __ldg(q4 + 1);      // Q0 w4,w5, pad, pad
    float acc0 = 0.f;
    float a0 = qa.x, a1 = qa.y, a2 = qa.z, a3 = qa.w, a4 = qb.x, a5 = qb.y;

#pragma unroll
    for (int i = 0; i < 3; i++) {
        float v = v1[i];
        float4 b0 = __ldg(q4 + 2 + i * 2);      // A1_i, B w0..2
        float4 b1 = __ldg(q4 + 3 + i * 2);      // B w3..5, pad
        acc0 += v * b0.x;
        a0 += v * b0.y; a1 += v * b0.z; a2 += v * b0.w;
        a3 += v * b1.x; a4 += v * b1.y; a5 += v * b1.z;
    }
#pragma unroll
    for (int i = 0; i < 5; i++) {
        float v = v2[i];
        float4 b0 = __ldg(q4 + 8 + i * 2);      // A2_i, B w0..2
        float4 b1 = __ldg(q4 + 9 + i * 2);      // B w3..5, pad
        acc0 += v * b0.x;
        a0 += v * b0.y; a1 += v * b0.z; a2 += v * b0.w;
        a3 += v * b1.x; a4 += v * b1.y; a5 += v * b1.z;
    }

    float* og = reinterpret_cast<float*>(g_out8) + (size_t)g * 8;
    red4(og + 0, acc0, a0, a1, a2);
    red4(og + 4, a3, a4, a5, 0.f);
}

// ============================================================================
// K5: copy padded accumulator -> out (5000 x 7); re-zero out8 for next replay
// ============================================================================
__global__ void k_final(float* __restrict__ out) {
    int i = blockIdx.x * blockDim.x + threadIdx.x;
    if (i >= NGR * 7) return;
    int g = i / 7, j = i - g * 7;
    float* o8 = reinterpret_cast<float*>(g_out8) + (size_t)g * 8;
    out[i] = o8[j];
    o8[j] = 0.f;
    if (j == 0) o8[7] = 0.f;
}

// ============================================================================
// Host: Wigner 3j (mirrors reference)
// ============================================================================
static double hfact(int n) { double r = 1.0; for (int i = 2; i <= n; i++) r *= (double)i; return r; }

static double hcg(int j1, int j2, int j3, int m1, int m2, int m3) {
    if (m1 + m2 != m3) return 0.0;
    double pre = sqrt((2.0 * j3 + 1.0) * hfact(j3 + j1 - j2) * hfact(j3 - j1 + j2) *
                      hfact(j1 + j2 - j3) / hfact(j1 + j2 + j3 + 1));
    pre *= sqrt(hfact(j3 + m3) * hfact(j3 - m3) * hfact(j1 - m1) * hfact(j1 + m1) *
                hfact(j2 - m2) * hfact(j2 + m2));
    int kmin = 0;
    if (j2 - j3 - m1 > kmin) kmin = j2 - j3 - m1;
    if (j1 - j3 + m2 > kmin) kmin = j1 - j3 + m2;
    int kmax = j1 + j2 - j3;
    if (j1 - m1 < kmax) kmax = j1 - m1;
    if (j2 + m2 < kmax) kmax = j2 + m2;
    double s = 0.0;
    for (int k = kmin; k <= kmax; k++) {
        double den = hfact(k) * hfact(j1 + j2 - j3 - k) * hfact(j1 - m1 - k) *
                     hfact(j2 + m2 - k) * hfact(j3 - j2 + m1 + k) * hfact(j3 - j1 - m2 + k);
        s += ((k & 1) ? -1.0 : 1.0) / den;
    }
    return pre * s;
}

static void humat(int l, double Ur[5][5], double Ui[5][5]) {
    for (int a = 0; a < 5; a++) for (int b = 0; b < 5; b++) { Ur[a][b] = 0.0; Ui[a][b] = 0.0; }
    double is2 = 1.0 / sqrt(2.0);
    for (int m = -l; m <= l; m++) {
        int r = m + l;
        if (m > 0) {
            Ur[r][l - m] = is2;
            Ur[r][l + m] = ((m & 1) ? -1.0 : 1.0) * is2;
        } else if (m == 0) {
            Ur[l][l] = 1.0;
        } else {
            Ui[r][l + m] = is2;
            Ui[r][l - m] = -(((-m) & 1) ? -1.0 : 1.0) * is2;
        }
    }
}

static void hw3j(int l1, int l2, int l3, float* out) {
    int n1 = 2 * l1 + 1, n2 = 2 * l2 + 1, n3 = 2 * l3 + 1;
    double C[5][5][5];
    memset(C, 0, sizeof(C));
    for (int m1 = -l1; m1 <= l1; m1++)
        for (int m2 = -l2; m2 <= l2; m2++) {
            int m3 = m1 + m2;
            if (m3 < -l3 || m3 > l3) continue;
            C[m1 + l1][m2 + l2][m3 + l3] = hcg(l1, l2, l3, m1, m2, m3);
        }
    double U1r[5][5], U1i[5][5], U2r[5][5], U2i[5][5], U3r[5][5], U3i[5][5];
    humat(l1, U1r, U1i); humat(l2, U2r, U2i); humat(l3, U3r, U3i);
    double Tre[5][5][5], Tim[5][5][5];
    double maxr = 0.0, maxi = 0.0;
    for (int a = 0; a < n1; a++)
        for (int b = 0; b < n2; b++)
            for (int c = 0; c < n3; c++) {
                double sr = 0.0, si = 0.0;
                for (int m = 0; m < n1; m++)
                    for (int n = 0; n < n2; n++)
                        for (int o = 0; o < n3; o++) {
                            double cv = C[m][n][o];
                            if (cv == 0.0) continue;
                            double ar = U1r[a][m], ai = U1i[a][m];
                            double br = U2r[b][n], bi = U2i[b][n];
                            double qr = ar * br - ai * bi, qi = ar * bi + ai * br;
                            double cr = U3r[c][o], ci = -U3i[c][o];
                            double rr = qr * cr - qi * ci, ri = qr * ci + qi * cr;
                            sr += rr * cv; si += ri * cv;
                        }
                Tre[a][b][c] = sr; Tim[a][b][c] = si;
                if (fabs(sr) > maxr) maxr = fabs(sr);
                if (fabs(si) > maxi) maxi = fabs(si);
            }
    bool useR = (maxr >= maxi);
    double nrm = 0.0;
    for (int a = 0; a < n1; a++)
        for (int b = 0; b < n2; b++)
            for (int c = 0; c < n3; c++) {
                double v = useR ? Tre[a][b][c] : Tim[a][b][c];
                nrm += v * v;
            }
    nrm = sqrt(nrm);
    for (int a = 0; a < n1; a++)
        for (int b = 0; b < n2; b++)
            for (int c = 0; c < n3; c++) {
                double v = useR ? Tre[a][b][c] : Tim[a][b][c];
                out[(a * n2 + b) * n3 + c] = (float)(v / nrm);
            }
}

// ============================================================================
// kernel_launch
// ============================================================================
extern "C" void kernel_launch(void* const* d_in, const int* in_sizes, int n_in,
                              void* d_out, int out_size) {
    const float* pos   = (const float*)d_in[0];
    const int*   zarr  = (const int*)  d_in[1];
    const int*   batch = (const int*)  d_in[2];
    const int*   esrc  = (const int*)  d_in[3];
    const int*   edst  = (const int*)  d_in[4];
    const float* w1    = (const float*)d_in[5];
    const float* w2    = (const float*)d_in[6];
    float*       out   = (float*)d_out;
    int E = in_sizes[3];

    // ---- host precompute (capture-time only) ----
    float c000, c011[9], c022[25], c101[9], c110[9], c202[25], c220[25];
    TP1P P;
    hw3j(0, 0, 0, &c000);
    hw3j(0, 1, 1, c011);  hw3j(0, 2, 2, c022);
    hw3j(1, 0, 1, c101);  hw3j(1, 1, 0, c110);
    hw3j(2, 0, 2, c202);  hw3j(2, 2, 0, c220);
    hw3j(1, 1, 1, P.c111); hw3j(1, 1, 2, P.c112);
    hw3j(1, 2, 1, P.c121); hw3j(1, 2, 2, P.c122);
    hw3j(2, 1, 1, P.c211); hw3j(2, 1, 2, P.c212);
    hw3j(2, 2, 1, P.c221); hw3j(2, 2, 2, P.c222);
    P.c000 = c000;
    for (int k = 0; k < 3; k++) { P.d011[k] = c011[k * 3 + k]; P.d101[k] = c101[k * 3 + k]; P.d110[k] = c110[k * 3 + k]; }
    for (int k = 0; k < 5; k++) { P.d022[k] = c022[k * 5 + k]; P.d202[k] = c202[k * 5 + k]; P.d220[k] = c220[k * 5 + k]; }

    PREPP M;
    {
        const double fan1[5] = {48.0, 32.0, 64.0, 64.0, 32.0};
        const int l3c[5] = {0, 1, 1, 2, 2};
        for (int c = 0; c < 5; c++)
            M.s1[c] = (float)(4.0 * sqrt(2.0 * l3c[c] + 1.0) / sqrt(fan1[c]) / 3.0);
        M.s20 = (float)(2.0 / (sqrt(3.0) * sqrt(640.0)));
        M.s21 = (float)(2.0 / (sqrt(3.0) * sqrt(1664.0)));
        M.q0s = c000 * M.s21;
    }

    TP2P P2;
    memcpy(P2.d110, P.d110, sizeof(P2.d110));
    memcpy(P2.d220, P.d220, sizeof(P2.d220));

    int EB = (E + 255) / 256;

    // ---- pipeline (5 launches; zero-invariant maintained in-kernel) ----
    k_shp<<<EB + 64, 256>>>(pos, zarr, batch, esrc, edst, w1, w2, E, EB, M);
    k_tp1<<<EB, 256>>>(esrc, edst, E, P);
    k_q<<<NN / 2, 256>>>(zarr);
    k_tp2<<<EB, 256>>>(esrc, E, P2);
    k_final<<<(NGR * 7 + 255) / 256, 256>>>(out);
}